// round 4
// baseline (speedup 1.0000x reference)
#include <cuda_runtime.h>

#define N_NODES 100000
#define E_EDGES 1600000
#define D 64
#define PITCH 68     // node-kernel smem pitch (floats)
#define P2 68        // edge-kernel smem pitch (float2 units): 68 mod 16 == 4

// Scratch (device globals — no dynamic allocation allowed)
__device__ float g_acc[2 * N_NODES * D];   // [v-sums | u-sums]
__device__ float g_deg[2 * N_NODES];       // [deg_v | deg_u]
__device__ float g_hweb[N_NODES * D];      // h @ We_h^T + be

// ---------------------------------------------------------------------------
// Stage 1: scatter-add efeats into per-node sums (both directions) + degrees
// ---------------------------------------------------------------------------
__device__ __forceinline__ void red_add_v4(float* p, float4 f) {
    asm volatile("red.global.add.v4.f32 [%0], {%1,%2,%3,%4};"
                 :: "l"(p), "f"(f.x), "f"(f.y), "f"(f.z), "f"(f.w) : "memory");
}

__global__ void scatter_kernel(const float4* __restrict__ ef4,
                               const int* __restrict__ u,
                               const int* __restrict__ v) {
    int idx = blockIdx.x * blockDim.x + threadIdx.x;  // exactly E*16
    int e = idx >> 4;
    int c = idx & 15;
    float4 f = ef4[idx];
    int vv = v[e];
    int uu = u[e];
    red_add_v4(&g_acc[(vv << 6) + (c << 2)], f);
    red_add_v4(&g_acc[(N_NODES << 6) + (uu << 6) + (c << 2)], f);
    if (c == 0) {
        atomicAdd(&g_deg[vv], 1.0f);
        atomicAdd(&g_deg[N_NODES + uu], 1.0f);
    }
}

// ---------------------------------------------------------------------------
// Stage 2: per-node — means, h = relu(cat @ Wn^T + bn), hweb = h @ We_h^T + be
// ---------------------------------------------------------------------------
__global__ void node_kernel(const float* __restrict__ Wn,
                            const float* __restrict__ bn,
                            const float* __restrict__ We,
                            const float* __restrict__ be,
                            float* __restrict__ h_out) {
    extern __shared__ float smem[];
    float* A_s = smem;                 // [128][PITCH]
    float* B_s = smem + 128 * PITCH;   // [128][PITCH]

    int t = threadIdx.x;
    int nb = blockIdx.x * 64;

    {
        int nl = t >> 2, q = t & 3;
        int n = nb + nl;
        bool ok = (n < N_NODES);
        float rv = 0.f, ru = 0.f;
        if (ok) {
            rv = 1.0f / fmaxf(g_deg[n], 1.0f);
            ru = 1.0f / fmaxf(g_deg[N_NODES + n], 1.0f);
        }
#pragma unroll
        for (int i = 0; i < 8; i++) {
            int k4 = q + 4 * i;
            float4 f = make_float4(0.f, 0.f, 0.f, 0.f);
            float s = 0.f;
            if (ok) {
                if (k4 < 16) { f = ((const float4*)g_acc)[n * 16 + k4]; s = rv; }
                else         { f = ((const float4*)g_acc)[(N_NODES + n) * 16 + (k4 - 16)]; s = ru; }
            }
            int k = k4 << 2;
            A_s[(k + 0) * PITCH + nl] = f.x * s;
            A_s[(k + 1) * PITCH + nl] = f.y * s;
            A_s[(k + 2) * PITCH + nl] = f.z * s;
            A_s[(k + 3) * PITCH + nl] = f.w * s;
        }
    }
    {
        int o = t >> 2, q = t & 3;
#pragma unroll
        for (int i = 0; i < 8; i++) {
            int k4 = q + 4 * i;
            float4 f = ((const float4*)Wn)[o * 32 + k4];
            int k = k4 << 2;
            B_s[(k + 0) * PITCH + o] = f.x;
            B_s[(k + 1) * PITCH + o] = f.y;
            B_s[(k + 2) * PITCH + o] = f.z;
            B_s[(k + 3) * PITCH + o] = f.w;
        }
    }
    __syncthreads();

    int tx = t & 15, ty = t >> 4;
    float acc[4][4] = {};
#pragma unroll 8
    for (int k = 0; k < 128; k++) {
        float4 a = *reinterpret_cast<const float4*>(&A_s[k * PITCH + (tx << 2)]);
        float4 b = *reinterpret_cast<const float4*>(&B_s[k * PITCH + (ty << 2)]);
        float av[4] = {a.x, a.y, a.z, a.w};
        float bv[4] = {b.x, b.y, b.z, b.w};
#pragma unroll
        for (int i = 0; i < 4; i++)
#pragma unroll
            for (int j = 0; j < 4; j++)
                acc[i][j] = fmaf(av[i], bv[j], acc[i][j]);
    }

    float4 bnv = ((const float4*)bn)[ty];
    float bnb[4] = {bnv.x, bnv.y, bnv.z, bnv.w};
    float hv[4][4];
#pragma unroll
    for (int i = 0; i < 4; i++)
#pragma unroll
        for (int j = 0; j < 4; j++)
            hv[i][j] = fmaxf(acc[i][j] + bnb[j], 0.0f);

    __syncthreads();

    float* C_s = A_s;
    float* H_s = B_s;

#pragma unroll
    for (int i = 0; i < 4; i++) {
        int n = nb + (tx << 2) + i;
#pragma unroll
        for (int j = 0; j < 4; j++)
            H_s[((ty << 2) + j) * PITCH + (tx << 2) + i] = hv[i][j];
        if (n < N_NODES)
            *reinterpret_cast<float4*>(&h_out[n * 64 + (ty << 2)]) =
                make_float4(hv[i][0], hv[i][1], hv[i][2], hv[i][3]);
    }
    {
        int o2 = t >> 2, q = t & 3;
#pragma unroll
        for (int i = 0; i < 4; i++) {
            int k4 = q + 4 * i;
            float4 f = ((const float4*)We)[o2 * 32 + k4];
            int k = k4 << 2;
            C_s[(k + 0) * PITCH + o2] = f.x;
            C_s[(k + 1) * PITCH + o2] = f.y;
            C_s[(k + 2) * PITCH + o2] = f.z;
            C_s[(k + 3) * PITCH + o2] = f.w;
        }
    }
    __syncthreads();

    float acc2[4][4] = {};
#pragma unroll 8
    for (int k = 0; k < 64; k++) {
        float4 a = *reinterpret_cast<const float4*>(&H_s[k * PITCH + (tx << 2)]);
        float4 b = *reinterpret_cast<const float4*>(&C_s[k * PITCH + (ty << 2)]);
        float av[4] = {a.x, a.y, a.z, a.w};
        float bv[4] = {b.x, b.y, b.z, b.w};
#pragma unroll
        for (int i = 0; i < 4; i++)
#pragma unroll
            for (int j = 0; j < 4; j++)
                acc2[i][j] = fmaf(av[i], bv[j], acc2[i][j]);
    }

    float4 bev = ((const float4*)be)[ty];
    float beb[4] = {bev.x, bev.y, bev.z, bev.w};
#pragma unroll
    for (int i = 0; i < 4; i++) {
        int n = nb + (tx << 2) + i;
        if (n < N_NODES)
            *reinterpret_cast<float4*>(&g_hweb[n * 64 + (ty << 2)]) =
                make_float4(acc2[i][0] + beb[0], acc2[i][1] + beb[1],
                            acc2[i][2] + beb[2], acc2[i][3] + beb[3]);
    }
}

// ---------------------------------------------------------------------------
// Stage 3: per-edge — edge = hweb[u[e]] + efeats[e] @ We_e^T  (3xTF32 mma)
// 256 threads (8 warps: 4m x 2n), 128-edge x 64-out block tile.
// A and B pre-split into tf32 (hi,lo) float2 pairs in smem at fill time:
// mainloop = LDS.64 + HMMA only (no cvt).
// ---------------------------------------------------------------------------
__device__ __forceinline__ unsigned cvt_tf32(float x) {
    unsigned r;
    asm("cvt.rna.tf32.f32 %0, %1;" : "=r"(r) : "f"(x));
    return r;
}
__device__ __forceinline__ float2 split_tf32(float x) {
    unsigned h = cvt_tf32(x);
    float hf = __uint_as_float(h);
    unsigned l = cvt_tf32(x - hf);
    return make_float2(hf, __uint_as_float(l));
}
__device__ __forceinline__ void mma_tf32(float c[4], const unsigned a[4], const unsigned b[2]) {
    asm volatile(
        "mma.sync.aligned.m16n8k8.row.col.f32.tf32.tf32.f32 "
        "{%0,%1,%2,%3}, {%4,%5,%6,%7}, {%8,%9}, {%0,%1,%2,%3};"
        : "+f"(c[0]), "+f"(c[1]), "+f"(c[2]), "+f"(c[3])
        : "r"(a[0]), "r"(a[1]), "r"(a[2]), "r"(a[3]), "r"(b[0]), "r"(b[1]));
}

__global__ void __launch_bounds__(256, 2)
edge_kernel(const float* __restrict__ efeats,
            const int* __restrict__ u,
            const float* __restrict__ We,
            float* __restrict__ edge_out) {
    extern __shared__ float2 smem2[];
    float2* A2 = smem2;              // [128][P2]  (hi,lo) per element
    float2* B2 = smem2 + 128 * P2;   // [64][P2]
    int* u_s = (int*)(B2 + 64 * P2); // [128]

    int t = threadIdx.x;
    int eb = blockIdx.x * 128;

    if (t < 128) u_s[t] = u[eb + t];

    // A fill: thread t handles half a row (32 floats), split to (hi,lo)
    {
        int e = t >> 1, half = t & 1;
        const float4* erow = (const float4*)efeats + (size_t)(eb + e) * 16 + half * 8;
        float2* dst = &A2[e * P2 + half * 32];
#pragma unroll
        for (int i = 0; i < 8; i++) {
            float4 f = erow[i];
            dst[i * 4 + 0] = split_tf32(f.x);
            dst[i * 4 + 1] = split_tf32(f.y);
            dst[i * 4 + 2] = split_tf32(f.z);
            dst[i * 4 + 3] = split_tf32(f.w);
        }
    }
    // B fill: We_e = We[:, 64:128] row o, split to (hi,lo)
    {
        int o = t >> 2, q = t & 3;
        const float4* wrow = (const float4*)We + o * 32 + 16 + q * 4;
        float2* dst = &B2[o * P2 + q * 16];
#pragma unroll
        for (int i = 0; i < 4; i++) {
            float4 f = wrow[i];
            dst[i * 4 + 0] = split_tf32(f.x);
            dst[i * 4 + 1] = split_tf32(f.y);
            dst[i * 4 + 2] = split_tf32(f.z);
            dst[i * 4 + 3] = split_tf32(f.w);
        }
    }
    __syncthreads();

    int wid = t >> 5, lane = t & 31;
    int wm = wid & 3;        // edges wm*32 .. +31
    int wn = wid >> 2;       // outs  wn*32 .. +31
    int g  = lane >> 2;      // group id (0..7)
    int tg = lane & 3;       // thread in group (0..3)

    float c[2][4][4] = {};   // [m-tile][n-tile][frag]

#pragma unroll 2
    for (int ks = 0; ks < 8; ks++) {
        int k0 = ks * 8;
        unsigned ah[2][4], al[2][4];
#pragma unroll
        for (int mt = 0; mt < 2; mt++) {
            int rb = wm * 32 + mt * 16;
            float2 p0 = A2[(rb + g) * P2 + k0 + tg];
            float2 p1 = A2[(rb + g + 8) * P2 + k0 + tg];
            float2 p2 = A2[(rb + g) * P2 + k0 + tg + 4];
            float2 p3 = A2[(rb + g + 8) * P2 + k0 + tg + 4];
            ah[mt][0] = __float_as_uint(p0.x); al[mt][0] = __float_as_uint(p0.y);
            ah[mt][1] = __float_as_uint(p1.x); al[mt][1] = __float_as_uint(p1.y);
            ah[mt][2] = __float_as_uint(p2.x); al[mt][2] = __float_as_uint(p2.y);
            ah[mt][3] = __float_as_uint(p3.x); al[mt][3] = __float_as_uint(p3.y);
        }
        unsigned bh[4][2], bl[4][2];
#pragma unroll
        for (int nt = 0; nt < 4; nt++) {
            int n = wn * 32 + nt * 8 + g;
            float2 q0 = B2[n * P2 + k0 + tg];
            float2 q1 = B2[n * P2 + k0 + tg + 4];
            bh[nt][0] = __float_as_uint(q0.x); bl[nt][0] = __float_as_uint(q0.y);
            bh[nt][1] = __float_as_uint(q1.x); bl[nt][1] = __float_as_uint(q1.y);
        }
#pragma unroll
        for (int mt = 0; mt < 2; mt++)
#pragma unroll
            for (int nt = 0; nt < 4; nt++) {
                mma_tf32(c[mt][nt], ah[mt], bh[nt]);  // hi*hi
                mma_tf32(c[mt][nt], ah[mt], bl[nt]);  // hi*lo
                mma_tf32(c[mt][nt], al[mt], bh[nt]);  // lo*hi
            }
    }

    // Epilogue: add gathered hweb[u[e]], store
#pragma unroll
    for (int mt = 0; mt < 2; mt++) {
        int r0 = wm * 32 + mt * 16 + g;
        int r1 = r0 + 8;
        int u0 = u_s[r0], u1 = u_s[r1];
        size_t e0 = (size_t)(eb + r0), e1 = (size_t)(eb + r1);
#pragma unroll
        for (int nt = 0; nt < 4; nt++) {
            int col = wn * 32 + nt * 8 + 2 * tg;
            float2 g0 = *(const float2*)&g_hweb[u0 * 64 + col];
            float2 g1 = *(const float2*)&g_hweb[u1 * 64 + col];
            *(float2*)&edge_out[e0 * 64 + col] =
                make_float2(c[mt][nt][0] + g0.x, c[mt][nt][1] + g0.y);
            *(float2*)&edge_out[e1 * 64 + col] =
                make_float2(c[mt][nt][2] + g1.x, c[mt][nt][3] + g1.y);
        }
    }
}

// ---------------------------------------------------------------------------
extern "C" void kernel_launch(void* const* d_in, const int* in_sizes, int n_in,
                              void* d_out, int out_size) {
    // inputs: [0]=nfeats (unused), [1]=efeats, [2]=u, [3]=v, [4]=Wn, [5]=bn, [6]=We, [7]=be
    const float* efeats = (const float*)d_in[1];
    const int*   u      = (const int*)d_in[2];
    const int*   v      = (const int*)d_in[3];
    const float* Wn     = (const float*)d_in[4];
    const float* bn     = (const float*)d_in[5];
    const float* We     = (const float*)d_in[6];
    const float* be     = (const float*)d_in[7];

    float* out      = (float*)d_out;
    float* h_out    = out;                               // [N,64]
    float* edge_out = out + (size_t)N_NODES * 64;        // [E,64]

    void* accp = nullptr; cudaGetSymbolAddress(&accp, g_acc);
    void* degp = nullptr; cudaGetSymbolAddress(&degp, g_deg);
    cudaMemsetAsync(accp, 0, sizeof(float) * 2 * N_NODES * D, 0);
    cudaMemsetAsync(degp, 0, sizeof(float) * 2 * N_NODES, 0);

    scatter_kernel<<<(E_EDGES * 16) / 256, 256>>>((const float4*)efeats, u, v);

    int node_smem = 2 * 128 * PITCH * (int)sizeof(float);  // 69632 B
    cudaFuncSetAttribute(node_kernel, cudaFuncAttributeMaxDynamicSharedMemorySize, node_smem);
    node_kernel<<<(N_NODES + 63) / 64, 256, node_smem>>>(Wn, bn, We, be, h_out);

    int edge_smem = (128 * P2 + 64 * P2) * (int)sizeof(float2) + 128 * (int)sizeof(int);  // ~105 KB
    cudaFuncSetAttribute(edge_kernel, cudaFuncAttributeMaxDynamicSharedMemorySize, edge_smem);
    edge_kernel<<<E_EDGES / 128, 256, edge_smem>>>(efeats, u, We, edge_out);
}

// round 7
// speedup vs baseline: 1.1906x; 1.1906x over previous
#include <cuda_runtime.h>
#include <cuda_bf16.h>
#include <cstdint>

#define N_NODES 100000
#define E_EDGES 1600000
#define D 64
#define PITCH 68     // node-kernel smem pitch (floats)
#define EPA 72       // edge-kernel bf16 row pitch (144 B)

// Scratch (device globals — no dynamic allocation allowed)
__device__ float g_acc[2 * N_NODES * D];   // [v-sums | u-sums]
__device__ float g_deg[2 * N_NODES];       // [deg_v | deg_u]
__device__ float g_hweb[N_NODES * D];      // h @ We_h^T + be

extern __shared__ char smem_raw[];

// ---------------------------------------------------------------------------
// Stage 1: scatter-add efeats into per-node sums (both directions) + degrees
// ---------------------------------------------------------------------------
__device__ __forceinline__ void red_add_v4(float* p, float4 f) {
    asm volatile("red.global.add.v4.f32 [%0], {%1,%2,%3,%4};"
                 :: "l"(p), "f"(f.x), "f"(f.y), "f"(f.z), "f"(f.w) : "memory");
}

__global__ void scatter_kernel(const float4* __restrict__ ef4,
                               const int* __restrict__ u,
                               const int* __restrict__ v) {
    int idx = blockIdx.x * blockDim.x + threadIdx.x;  // exactly E*16
    int e = idx >> 4;
    int c = idx & 15;
    float4 f = ef4[idx];
    int vv = v[e];
    int uu = u[e];
    red_add_v4(&g_acc[(vv << 6) + (c << 2)], f);
    red_add_v4(&g_acc[(N_NODES << 6) + (uu << 6) + (c << 2)], f);
    if (c == 0) {
        atomicAdd(&g_deg[vv], 1.0f);
        atomicAdd(&g_deg[N_NODES + uu], 1.0f);
    }
}

// ---------------------------------------------------------------------------
// Stage 2: per-node — means, h = relu(cat @ Wn^T + bn), hweb = h @ We_h^T + be
// ---------------------------------------------------------------------------
__global__ void node_kernel(const float* __restrict__ Wn,
                            const float* __restrict__ bn,
                            const float* __restrict__ We,
                            const float* __restrict__ be,
                            float* __restrict__ h_out) {
    float* smem = (float*)smem_raw;
    float* A_s = smem;                 // [128][PITCH]
    float* B_s = smem + 128 * PITCH;   // [128][PITCH]

    int t = threadIdx.x;
    int nb = blockIdx.x * 64;

    {
        int nl = t >> 2, q = t & 3;
        int n = nb + nl;
        bool ok = (n < N_NODES);
        float rv = 0.f, ru = 0.f;
        if (ok) {
            rv = 1.0f / fmaxf(g_deg[n], 1.0f);
            ru = 1.0f / fmaxf(g_deg[N_NODES + n], 1.0f);
        }
#pragma unroll
        for (int i = 0; i < 8; i++) {
            int k4 = q + 4 * i;
            float4 f = make_float4(0.f, 0.f, 0.f, 0.f);
            float s = 0.f;
            if (ok) {
                if (k4 < 16) { f = ((const float4*)g_acc)[n * 16 + k4]; s = rv; }
                else         { f = ((const float4*)g_acc)[(N_NODES + n) * 16 + (k4 - 16)]; s = ru; }
            }
            int k = k4 << 2;
            A_s[(k + 0) * PITCH + nl] = f.x * s;
            A_s[(k + 1) * PITCH + nl] = f.y * s;
            A_s[(k + 2) * PITCH + nl] = f.z * s;
            A_s[(k + 3) * PITCH + nl] = f.w * s;
        }
    }
    {
        int o = t >> 2, q = t & 3;
#pragma unroll
        for (int i = 0; i < 8; i++) {
            int k4 = q + 4 * i;
            float4 f = ((const float4*)Wn)[o * 32 + k4];
            int k = k4 << 2;
            B_s[(k + 0) * PITCH + o] = f.x;
            B_s[(k + 1) * PITCH + o] = f.y;
            B_s[(k + 2) * PITCH + o] = f.z;
            B_s[(k + 3) * PITCH + o] = f.w;
        }
    }
    __syncthreads();

    int tx = t & 15, ty = t >> 4;
    float acc[4][4] = {};
#pragma unroll 8
    for (int k = 0; k < 128; k++) {
        float4 a = *reinterpret_cast<const float4*>(&A_s[k * PITCH + (tx << 2)]);
        float4 b = *reinterpret_cast<const float4*>(&B_s[k * PITCH + (ty << 2)]);
        float av[4] = {a.x, a.y, a.z, a.w};
        float bv[4] = {b.x, b.y, b.z, b.w};
#pragma unroll
        for (int i = 0; i < 4; i++)
#pragma unroll
            for (int j = 0; j < 4; j++)
                acc[i][j] = fmaf(av[i], bv[j], acc[i][j]);
    }

    float4 bnv = ((const float4*)bn)[ty];
    float bnb[4] = {bnv.x, bnv.y, bnv.z, bnv.w};
    float hv[4][4];
#pragma unroll
    for (int i = 0; i < 4; i++)
#pragma unroll
        for (int j = 0; j < 4; j++)
            hv[i][j] = fmaxf(acc[i][j] + bnb[j], 0.0f);

    __syncthreads();

    float* C_s = A_s;
    float* H_s = B_s;

#pragma unroll
    for (int i = 0; i < 4; i++) {
        int n = nb + (tx << 2) + i;
#pragma unroll
        for (int j = 0; j < 4; j++)
            H_s[((ty << 2) + j) * PITCH + (tx << 2) + i] = hv[i][j];
        if (n < N_NODES)
            *reinterpret_cast<float4*>(&h_out[n * 64 + (ty << 2)]) =
                make_float4(hv[i][0], hv[i][1], hv[i][2], hv[i][3]);
    }
    {
        int o2 = t >> 2, q = t & 3;
#pragma unroll
        for (int i = 0; i < 4; i++) {
            int k4 = q + 4 * i;
            float4 f = ((const float4*)We)[o2 * 32 + k4];
            int k = k4 << 2;
            C_s[(k + 0) * PITCH + o2] = f.x;
            C_s[(k + 1) * PITCH + o2] = f.y;
            C_s[(k + 2) * PITCH + o2] = f.z;
            C_s[(k + 3) * PITCH + o2] = f.w;
        }
    }
    __syncthreads();

    float acc2[4][4] = {};
#pragma unroll 8
    for (int k = 0; k < 64; k++) {
        float4 a = *reinterpret_cast<const float4*>(&H_s[k * PITCH + (tx << 2)]);
        float4 b = *reinterpret_cast<const float4*>(&C_s[k * PITCH + (ty << 2)]);
        float av[4] = {a.x, a.y, a.z, a.w};
        float bv[4] = {b.x, b.y, b.z, b.w};
#pragma unroll
        for (int i = 0; i < 4; i++)
#pragma unroll
            for (int j = 0; j < 4; j++)
                acc2[i][j] = fmaf(av[i], bv[j], acc2[i][j]);
    }

    float4 bev = ((const float4*)be)[ty];
    float beb[4] = {bev.x, bev.y, bev.z, bev.w};
#pragma unroll
    for (int i = 0; i < 4; i++) {
        int n = nb + (tx << 2) + i;
        if (n < N_NODES)
            *reinterpret_cast<float4*>(&g_hweb[n * 64 + (ty << 2)]) =
                make_float4(acc2[i][0] + beb[0], acc2[i][1] + beb[1],
                            acc2[i][2] + beb[2], acc2[i][3] + beb[3]);
    }
}

// ---------------------------------------------------------------------------
// Stage 3: edge = hweb[u[e]] + efeats[e] @ We_e^T   (bf16x3 legacy mma)
// 256 threads (8 warps: 4m x 2n), 128-edge x 64-out tile.
// A/B pre-split into bf16 (hi,lo) buffers at fill time; mainloop = LDS + HMMA.
// ---------------------------------------------------------------------------
__device__ __forceinline__ void mma_bf16(float c[4], const unsigned a[4], const unsigned b[2]) {
    asm volatile(
        "mma.sync.aligned.m16n8k16.row.col.f32.bf16.bf16.f32 "
        "{%0,%1,%2,%3}, {%4,%5,%6,%7}, {%8,%9}, {%0,%1,%2,%3};"
        : "+f"(c[0]), "+f"(c[1]), "+f"(c[2]), "+f"(c[3])
        : "r"(a[0]), "r"(a[1]), "r"(a[2]), "r"(a[3]), "r"(b[0]), "r"(b[1]));
}
__device__ __forceinline__ unsigned pack_hi(float x, float y) {
    __nv_bfloat162 h(__float2bfloat16_rn(x), __float2bfloat16_rn(y));
    return *(unsigned*)&h;
}
__device__ __forceinline__ unsigned pack_lo(float x, float y) {
    __nv_bfloat16 hx = __float2bfloat16_rn(x), hy = __float2bfloat16_rn(y);
    __nv_bfloat162 l(__float2bfloat16_rn(x - __bfloat162float(hx)),
                     __float2bfloat16_rn(y - __bfloat162float(hy)));
    return *(unsigned*)&l;
}

// smem layout (bf16 elements / bytes)
#define SM_AHI 0                      // [128][EPA] bf16 = 18432 B
#define SM_ALO (128 * EPA)            // +18432
#define SM_BHI (2 * 128 * EPA)        // [64][EPA]  = 9216 B
#define SM_BLO (2 * 128 * EPA + 64 * EPA)
#define SM_U_OFF (2 * 128 * EPA + 2 * 64 * EPA)   // bf16 units; int[128] after
#define SM_EDGE_BYTES (SM_U_OFF * 2 + 128 * 4)    // 55808 B

__global__ void __launch_bounds__(256, 4)
edge_kernel(const float* __restrict__ efeats,
            const int* __restrict__ u,
            const float* __restrict__ We,
            float* __restrict__ edge_out) {
    __nv_bfloat16* bs = (__nv_bfloat16*)smem_raw;
    __nv_bfloat16* A_hi = bs + SM_AHI;
    __nv_bfloat16* A_lo = bs + SM_ALO;
    __nv_bfloat16* B_hi = bs + SM_BHI;
    __nv_bfloat16* B_lo = bs + SM_BLO;
    int* u_s = (int*)(bs + SM_U_OFF);

    int t = threadIdx.x;
    int eb = blockIdx.x * 128;

    if (t < 128) u_s[t] = u[eb + t];

    // ---- A fill: thread t does half a row (32 floats) -> bf16 hi/lo
    {
        int row = t >> 1, half = t & 1;
        const float4* src = (const float4*)efeats + (size_t)(eb + row) * 16 + half * 8;
        unsigned* dh = (unsigned*)&A_hi[row * EPA + half * 32];
        unsigned* dl = (unsigned*)&A_lo[row * EPA + half * 32];
#pragma unroll
        for (int i = 0; i < 8; i++) {
            float4 f = src[i];
            dh[i * 2 + 0] = pack_hi(f.x, f.y);
            dh[i * 2 + 1] = pack_hi(f.z, f.w);
            dl[i * 2 + 0] = pack_lo(f.x, f.y);
            dl[i * 2 + 1] = pack_lo(f.z, f.w);
        }
    }
    // ---- B fill: We_e = We[:, 64:128]; thread t does 16 cols of row o
    {
        int o = t >> 2, q = t & 3;
        const float4* src = (const float4*)We + o * 32 + 16 + q * 4;
        unsigned* dh = (unsigned*)&B_hi[o * EPA + q * 16];
        unsigned* dl = (unsigned*)&B_lo[o * EPA + q * 16];
#pragma unroll
        for (int i = 0; i < 4; i++) {
            float4 f = src[i];
            dh[i * 2 + 0] = pack_hi(f.x, f.y);
            dh[i * 2 + 1] = pack_hi(f.z, f.w);
            dl[i * 2 + 0] = pack_lo(f.x, f.y);
            dl[i * 2 + 1] = pack_lo(f.z, f.w);
        }
    }
    __syncthreads();

    int wid = t >> 5, lane = t & 31;
    int wm = wid & 3;        // edges wm*32 .. +31
    int wn = wid >> 2;       // outs  wn*32 .. +31
    int g  = lane >> 2;      // 0..7
    int tg = lane & 3;       // 0..3

    float c[2][4][4] = {};   // [m-tile][n-tile][frag]

#pragma unroll
    for (int ks = 0; ks < 4; ks++) {
        int k0 = ks * 16;
        unsigned ah[2][4], al[2][4];
#pragma unroll
        for (int mt = 0; mt < 2; mt++) {
            int rb = wm * 32 + mt * 16;
            ah[mt][0] = *(const unsigned*)&A_hi[(rb + g) * EPA + k0 + 2 * tg];
            ah[mt][1] = *(const unsigned*)&A_hi[(rb + 8 + g) * EPA + k0 + 2 * tg];
            ah[mt][2] = *(const unsigned*)&A_hi[(rb + g) * EPA + k0 + 8 + 2 * tg];
            ah[mt][3] = *(const unsigned*)&A_hi[(rb + 8 + g) * EPA + k0 + 8 + 2 * tg];
            al[mt][0] = *(const unsigned*)&A_lo[(rb + g) * EPA + k0 + 2 * tg];
            al[mt][1] = *(const unsigned*)&A_lo[(rb + 8 + g) * EPA + k0 + 2 * tg];
            al[mt][2] = *(const unsigned*)&A_lo[(rb + g) * EPA + k0 + 8 + 2 * tg];
            al[mt][3] = *(const unsigned*)&A_lo[(rb + 8 + g) * EPA + k0 + 8 + 2 * tg];
        }
        unsigned bh[4][2], bl[4][2];
#pragma unroll
        for (int nt = 0; nt < 4; nt++) {
            int n = wn * 32 + nt * 8 + g;
            bh[nt][0] = *(const unsigned*)&B_hi[n * EPA + k0 + 2 * tg];
            bh[nt][1] = *(const unsigned*)&B_hi[n * EPA + k0 + 8 + 2 * tg];
            bl[nt][0] = *(const unsigned*)&B_lo[n * EPA + k0 + 2 * tg];
            bl[nt][1] = *(const unsigned*)&B_lo[n * EPA + k0 + 8 + 2 * tg];
        }
#pragma unroll
        for (int mt = 0; mt < 2; mt++)
#pragma unroll
            for (int nt = 0; nt < 4; nt++) {
                mma_bf16(c[mt][nt], ah[mt], bh[nt]);  // hi*hi
                mma_bf16(c[mt][nt], ah[mt], bl[nt]);  // hi*lo
                mma_bf16(c[mt][nt], al[mt], bh[nt]);  // lo*hi
            }
    }

    // Epilogue: add gathered hweb[u[e]], store
#pragma unroll
    for (int mt = 0; mt < 2; mt++) {
        int r0 = wm * 32 + mt * 16 + g;
        int r1 = r0 + 8;
        int u0 = u_s[r0], u1 = u_s[r1];
        size_t e0 = (size_t)(eb + r0), e1 = (size_t)(eb + r1);
#pragma unroll
        for (int nt = 0; nt < 4; nt++) {
            int col = wn * 32 + nt * 8 + 2 * tg;
            float2 g0 = *(const float2*)&g_hweb[u0 * 64 + col];
            float2 g1 = *(const float2*)&g_hweb[u1 * 64 + col];
            *(float2*)&edge_out[e0 * 64 + col] =
                make_float2(c[mt][nt][0] + g0.x, c[mt][nt][1] + g0.y);
            *(float2*)&edge_out[e1 * 64 + col] =
                make_float2(c[mt][nt][2] + g1.x, c[mt][nt][3] + g1.y);
        }
    }
}

// ---------------------------------------------------------------------------
extern "C" void kernel_launch(void* const* d_in, const int* in_sizes, int n_in,
                              void* d_out, int out_size) {
    // inputs: [0]=nfeats (unused), [1]=efeats, [2]=u, [3]=v, [4]=Wn, [5]=bn, [6]=We, [7]=be
    const float* efeats = (const float*)d_in[1];
    const int*   u      = (const int*)d_in[2];
    const int*   v      = (const int*)d_in[3];
    const float* Wn     = (const float*)d_in[4];
    const float* bn     = (const float*)d_in[5];
    const float* We     = (const float*)d_in[6];
    const float* be     = (const float*)d_in[7];

    float* out      = (float*)d_out;
    float* h_out    = out;                               // [N,64]
    float* edge_out = out + (size_t)N_NODES * 64;        // [E,64]

    void* accp = nullptr; cudaGetSymbolAddress(&accp, g_acc);
    void* degp = nullptr; cudaGetSymbolAddress(&degp, g_deg);
    cudaMemsetAsync(accp, 0, sizeof(float) * 2 * N_NODES * D, 0);
    cudaMemsetAsync(degp, 0, sizeof(float) * 2 * N_NODES, 0);

    scatter_kernel<<<(E_EDGES * 16) / 256, 256>>>((const float4*)efeats, u, v);

    int node_smem = 2 * 128 * PITCH * (int)sizeof(float);  // 69632 B
    cudaFuncSetAttribute(node_kernel, cudaFuncAttributeMaxDynamicSharedMemorySize, node_smem);
    node_kernel<<<(N_NODES + 63) / 64, 256, node_smem>>>(Wn, bn, We, be, h_out);

    cudaFuncSetAttribute(edge_kernel, cudaFuncAttributeMaxDynamicSharedMemorySize, SM_EDGE_BYTES);
    edge_kernel<<<E_EDGES / 128, 256, SM_EDGE_BYTES>>>(efeats, u, We, edge_out);
}

// round 8
// speedup vs baseline: 1.3521x; 1.1357x over previous
#include <cuda_runtime.h>
#include <cuda_bf16.h>
#include <cstdint>

#define N_NODES 100000
#define E_EDGES 1600000
#define D 64
#define PITCH 68     // node-kernel smem pitch (floats)
#define EPA 72       // edge-kernel bf16 row pitch (144 B)

// Scratch (device globals — no dynamic allocation allowed)
__device__ float g_acc[2 * N_NODES * D];   // [v-sums | u-sums]
__device__ float g_deg[2 * N_NODES];       // [deg_v | deg_u]
__device__ float g_hweb[N_NODES * D];      // h @ We_h^T + be

extern __shared__ char smem_raw[];

// ---------------------------------------------------------------------------
// Stage 1: scatter-add efeats into per-node sums (both directions) + degrees
// ---------------------------------------------------------------------------
__device__ __forceinline__ void red_add_v4(float* p, float4 f) {
    asm volatile("red.global.add.v4.f32 [%0], {%1,%2,%3,%4};"
                 :: "l"(p), "f"(f.x), "f"(f.y), "f"(f.z), "f"(f.w) : "memory");
}

__global__ void scatter_kernel(const float4* __restrict__ ef4,
                               const int* __restrict__ u,
                               const int* __restrict__ v) {
    int idx = blockIdx.x * blockDim.x + threadIdx.x;  // exactly E*16
    int e = idx >> 4;
    int c = idx & 15;
    float4 f = ef4[idx];
    int vv = v[e];
    int uu = u[e];
    red_add_v4(&g_acc[(vv << 6) + (c << 2)], f);
    red_add_v4(&g_acc[(N_NODES << 6) + (uu << 6) + (c << 2)], f);
    if (c == 0) {
        atomicAdd(&g_deg[vv], 1.0f);
        atomicAdd(&g_deg[N_NODES + uu], 1.0f);
    }
}

// ---------------------------------------------------------------------------
// Stage 2: per-node — means, h = relu(cat @ Wn^T + bn), hweb = h @ We_h^T + be
// ---------------------------------------------------------------------------
__global__ void node_kernel(const float* __restrict__ Wn,
                            const float* __restrict__ bn,
                            const float* __restrict__ We,
                            const float* __restrict__ be,
                            float* __restrict__ h_out) {
    float* smem = (float*)smem_raw;
    float* A_s = smem;                 // [128][PITCH]
    float* B_s = smem + 128 * PITCH;   // [128][PITCH]

    int t = threadIdx.x;
    int nb = blockIdx.x * 64;

    {
        int nl = t >> 2, q = t & 3;
        int n = nb + nl;
        bool ok = (n < N_NODES);
        float rv = 0.f, ru = 0.f;
        if (ok) {
            rv = 1.0f / fmaxf(g_deg[n], 1.0f);
            ru = 1.0f / fmaxf(g_deg[N_NODES + n], 1.0f);
        }
#pragma unroll
        for (int i = 0; i < 8; i++) {
            int k4 = q + 4 * i;
            float4 f = make_float4(0.f, 0.f, 0.f, 0.f);
            float s = 0.f;
            if (ok) {
                if (k4 < 16) { f = ((const float4*)g_acc)[n * 16 + k4]; s = rv; }
                else         { f = ((const float4*)g_acc)[(N_NODES + n) * 16 + (k4 - 16)]; s = ru; }
            }
            int k = k4 << 2;
            A_s[(k + 0) * PITCH + nl] = f.x * s;
            A_s[(k + 1) * PITCH + nl] = f.y * s;
            A_s[(k + 2) * PITCH + nl] = f.z * s;
            A_s[(k + 3) * PITCH + nl] = f.w * s;
        }
    }
    {
        int o = t >> 2, q = t & 3;
#pragma unroll
        for (int i = 0; i < 8; i++) {
            int k4 = q + 4 * i;
            float4 f = ((const float4*)Wn)[o * 32 + k4];
            int k = k4 << 2;
            B_s[(k + 0) * PITCH + o] = f.x;
            B_s[(k + 1) * PITCH + o] = f.y;
            B_s[(k + 2) * PITCH + o] = f.z;
            B_s[(k + 3) * PITCH + o] = f.w;
        }
    }
    __syncthreads();

    int tx = t & 15, ty = t >> 4;
    float acc[4][4] = {};
#pragma unroll 8
    for (int k = 0; k < 128; k++) {
        float4 a = *reinterpret_cast<const float4*>(&A_s[k * PITCH + (tx << 2)]);
        float4 b = *reinterpret_cast<const float4*>(&B_s[k * PITCH + (ty << 2)]);
        float av[4] = {a.x, a.y, a.z, a.w};
        float bv[4] = {b.x, b.y, b.z, b.w};
#pragma unroll
        for (int i = 0; i < 4; i++)
#pragma unroll
            for (int j = 0; j < 4; j++)
                acc[i][j] = fmaf(av[i], bv[j], acc[i][j]);
    }

    float4 bnv = ((const float4*)bn)[ty];
    float bnb[4] = {bnv.x, bnv.y, bnv.z, bnv.w};
    float hv[4][4];
#pragma unroll
    for (int i = 0; i < 4; i++)
#pragma unroll
        for (int j = 0; j < 4; j++)
            hv[i][j] = fmaxf(acc[i][j] + bnb[j], 0.0f);

    __syncthreads();

    float* C_s = A_s;
    float* H_s = B_s;

#pragma unroll
    for (int i = 0; i < 4; i++) {
        int n = nb + (tx << 2) + i;
#pragma unroll
        for (int j = 0; j < 4; j++)
            H_s[((ty << 2) + j) * PITCH + (tx << 2) + i] = hv[i][j];
        if (n < N_NODES)
            *reinterpret_cast<float4*>(&h_out[n * 64 + (ty << 2)]) =
                make_float4(hv[i][0], hv[i][1], hv[i][2], hv[i][3]);
    }
    {
        int o2 = t >> 2, q = t & 3;
#pragma unroll
        for (int i = 0; i < 4; i++) {
            int k4 = q + 4 * i;
            float4 f = ((const float4*)We)[o2 * 32 + k4];
            int k = k4 << 2;
            C_s[(k + 0) * PITCH + o2] = f.x;
            C_s[(k + 1) * PITCH + o2] = f.y;
            C_s[(k + 2) * PITCH + o2] = f.z;
            C_s[(k + 3) * PITCH + o2] = f.w;
        }
    }
    __syncthreads();

    float acc2[4][4] = {};
#pragma unroll 8
    for (int k = 0; k < 64; k++) {
        float4 a = *reinterpret_cast<const float4*>(&H_s[k * PITCH + (tx << 2)]);
        float4 b = *reinterpret_cast<const float4*>(&C_s[k * PITCH + (ty << 2)]);
        float av[4] = {a.x, a.y, a.z, a.w};
        float bv[4] = {b.x, b.y, b.z, b.w};
#pragma unroll
        for (int i = 0; i < 4; i++)
#pragma unroll
            for (int j = 0; j < 4; j++)
                acc2[i][j] = fmaf(av[i], bv[j], acc2[i][j]);
    }

    float4 bev = ((const float4*)be)[ty];
    float beb[4] = {bev.x, bev.y, bev.z, bev.w};
#pragma unroll
    for (int i = 0; i < 4; i++) {
        int n = nb + (tx << 2) + i;
        if (n < N_NODES)
            *reinterpret_cast<float4*>(&g_hweb[n * 64 + (ty << 2)]) =
                make_float4(acc2[i][0] + beb[0], acc2[i][1] + beb[1],
                            acc2[i][2] + beb[2], acc2[i][3] + beb[3]);
    }
}

// ---------------------------------------------------------------------------
// Stage 3: edge = hweb[u[e]] + efeats[e] @ We_e^T   (bf16x3 legacy mma)
// 256 threads (8 warps: 4m x 2n), 128-edge x 64-out tile.
// ldmatrix fragment loads; occupancy 3 (85-reg budget, no mainloop spills).
// ---------------------------------------------------------------------------
__device__ __forceinline__ void mma_bf16(float c[4], const unsigned a[4], const unsigned b[2]) {
    asm volatile(
        "mma.sync.aligned.m16n8k16.row.col.f32.bf16.bf16.f32 "
        "{%0,%1,%2,%3}, {%4,%5,%6,%7}, {%8,%9}, {%0,%1,%2,%3};"
        : "+f"(c[0]), "+f"(c[1]), "+f"(c[2]), "+f"(c[3])
        : "r"(a[0]), "r"(a[1]), "r"(a[2]), "r"(a[3]), "r"(b[0]), "r"(b[1]));
}
__device__ __forceinline__ void ldsm_x4(unsigned r[4], uint32_t addr) {
    asm volatile("ldmatrix.sync.aligned.m8n8.x4.shared.b16 {%0,%1,%2,%3}, [%4];"
                 : "=r"(r[0]), "=r"(r[1]), "=r"(r[2]), "=r"(r[3]) : "r"(addr));
}
__device__ __forceinline__ void ldsm_x2(unsigned r[2], uint32_t addr) {
    asm volatile("ldmatrix.sync.aligned.m8n8.x2.shared.b16 {%0,%1}, [%2];"
                 : "=r"(r[0]), "=r"(r[1]) : "r"(addr));
}
__device__ __forceinline__ unsigned pack_hi(float x, float y) {
    __nv_bfloat162 h(__float2bfloat16_rn(x), __float2bfloat16_rn(y));
    return *(unsigned*)&h;
}
__device__ __forceinline__ unsigned pack_lo(float x, float y) {
    __nv_bfloat16 hx = __float2bfloat16_rn(x), hy = __float2bfloat16_rn(y);
    __nv_bfloat162 l(__float2bfloat16_rn(x - __bfloat162float(hx)),
                     __float2bfloat16_rn(y - __bfloat162float(hy)));
    return *(unsigned*)&l;
}
static __device__ __forceinline__ uint32_t smem_u32e(const void* p) {
    uint32_t a;
    asm("{ .reg .u64 t; cvta.to.shared.u64 t, %1; cvt.u32.u64 %0, t; }" : "=r"(a) : "l"(p));
    return a;
}

// smem layout (bf16 elements / bytes)
#define SM_AHI 0                      // [128][EPA] bf16 = 18432 B
#define SM_ALO (128 * EPA)            // +18432
#define SM_BHI (2 * 128 * EPA)        // [64][EPA]  = 9216 B
#define SM_BLO (2 * 128 * EPA + 64 * EPA)
#define SM_U_OFF (2 * 128 * EPA + 2 * 64 * EPA)   // bf16 units; int[128] after
#define SM_EDGE_BYTES (SM_U_OFF * 2 + 128 * 4)    // 55808 B

__global__ void __launch_bounds__(256, 3)
edge_kernel(const float* __restrict__ efeats,
            const int* __restrict__ u,
            const float* __restrict__ We,
            float* __restrict__ edge_out) {
    __nv_bfloat16* bs = (__nv_bfloat16*)smem_raw;
    __nv_bfloat16* A_hi = bs + SM_AHI;
    __nv_bfloat16* A_lo = bs + SM_ALO;
    __nv_bfloat16* B_hi = bs + SM_BHI;
    __nv_bfloat16* B_lo = bs + SM_BLO;
    int* u_s = (int*)(bs + SM_U_OFF);

    int t = threadIdx.x;
    int eb = blockIdx.x * 128;

    if (t < 128) u_s[t] = u[eb + t];

    // ---- A fill: thread t does half a row (32 floats) -> bf16 hi/lo
    {
        int row = t >> 1, half = t & 1;
        const float4* src = (const float4*)efeats + (size_t)(eb + row) * 16 + half * 8;
        unsigned* dh = (unsigned*)&A_hi[row * EPA + half * 32];
        unsigned* dl = (unsigned*)&A_lo[row * EPA + half * 32];
#pragma unroll
        for (int i = 0; i < 8; i++) {
            float4 f = src[i];
            dh[i * 2 + 0] = pack_hi(f.x, f.y);
            dh[i * 2 + 1] = pack_hi(f.z, f.w);
            dl[i * 2 + 0] = pack_lo(f.x, f.y);
            dl[i * 2 + 1] = pack_lo(f.z, f.w);
        }
    }
    // ---- B fill: We_e = We[:, 64:128]; thread t does 16 cols of row o
    {
        int o = t >> 2, q = t & 3;
        const float4* src = (const float4*)We + o * 32 + 16 + q * 4;
        unsigned* dh = (unsigned*)&B_hi[o * EPA + q * 16];
        unsigned* dl = (unsigned*)&B_lo[o * EPA + q * 16];
#pragma unroll
        for (int i = 0; i < 4; i++) {
            float4 f = src[i];
            dh[i * 2 + 0] = pack_hi(f.x, f.y);
            dh[i * 2 + 1] = pack_hi(f.z, f.w);
            dl[i * 2 + 0] = pack_lo(f.x, f.y);
            dl[i * 2 + 1] = pack_lo(f.z, f.w);
        }
    }
    __syncthreads();

    int wid = t >> 5, lane = t & 31;
    int wm = wid & 3;        // edges wm*32 .. +31
    int wn = wid >> 2;       // outs  wn*32 .. +31
    int g  = lane >> 2;      // 0..7
    int tg = lane & 3;       // 0..3

    // ldmatrix per-lane base addresses (in bf16-element units before scaling)
    // A x4: row = rb + (lane & 15), col = k0 + (lane>>4)*8
    int a_row_off = lane & 15;
    int a_col_off = (lane >> 4) << 3;
    uint32_t ahi_base = smem_u32e(&A_hi[(wm * 32 + a_row_off) * EPA + a_col_off]);
    uint32_t alo_base = smem_u32e(&A_lo[(wm * 32 + a_row_off) * EPA + a_col_off]);
    // B x2: lanes 0-7: row n0+lane, col k0; lanes 8-15: row n0+lane-8, col k0+8
    int b_lane = lane & 15;
    int b_row_off = (b_lane < 8) ? b_lane : (b_lane - 8);
    int b_col_off = (b_lane < 8) ? 0 : 8;
    uint32_t bhi_base = smem_u32e(&B_hi[(wn * 32 + b_row_off) * EPA + b_col_off]);
    uint32_t blo_base = smem_u32e(&B_lo[(wn * 32 + b_row_off) * EPA + b_col_off]);

    float c[2][4][4] = {};   // [m-tile][n-tile][frag]

#pragma unroll
    for (int ks = 0; ks < 4; ks++) {
        uint32_t kb = ks * 32;  // k0 * sizeof(bf16)
        unsigned ah[2][4], al[2][4];
        ldsm_x4(ah[0], ahi_base + kb);
        ldsm_x4(ah[1], ahi_base + kb + 16 * EPA * 2);
        ldsm_x4(al[0], alo_base + kb);
        ldsm_x4(al[1], alo_base + kb + 16 * EPA * 2);
        unsigned bh[4][2], bl[4][2];
#pragma unroll
        for (int nt = 0; nt < 4; nt++) {
            ldsm_x2(bh[nt], bhi_base + kb + nt * 8 * EPA * 2);
            ldsm_x2(bl[nt], blo_base + kb + nt * 8 * EPA * 2);
        }
#pragma unroll
        for (int mt = 0; mt < 2; mt++)
#pragma unroll
            for (int nt = 0; nt < 4; nt++) {
                mma_bf16(c[mt][nt], ah[mt], bh[nt]);  // hi*hi
                mma_bf16(c[mt][nt], ah[mt], bl[nt]);  // hi*lo
                mma_bf16(c[mt][nt], al[mt], bh[nt]);  // lo*hi
            }
    }

    // Epilogue: add gathered hweb[u[e]], store
#pragma unroll
    for (int mt = 0; mt < 2; mt++) {
        int r0 = wm * 32 + mt * 16 + g;
        int r1 = r0 + 8;
        int u0 = u_s[r0], u1 = u_s[r1];
        size_t e0 = (size_t)(eb + r0), e1 = (size_t)(eb + r1);
#pragma unroll
        for (int nt = 0; nt < 4; nt++) {
            int col = wn * 32 + nt * 8 + 2 * tg;
            float2 g0 = *(const float2*)&g_hweb[u0 * 64 + col];
            float2 g1 = *(const float2*)&g_hweb[u1 * 64 + col];
            *(float2*)&edge_out[e0 * 64 + col] =
                make_float2(c[mt][nt][0] + g0.x, c[mt][nt][1] + g0.y);
            *(float2*)&edge_out[e1 * 64 + col] =
                make_float2(c[mt][nt][2] + g1.x, c[mt][nt][3] + g1.y);
        }
    }
}

// ---------------------------------------------------------------------------
extern "C" void kernel_launch(void* const* d_in, const int* in_sizes, int n_in,
                              void* d_out, int out_size) {
    // inputs: [0]=nfeats (unused), [1]=efeats, [2]=u, [3]=v, [4]=Wn, [5]=bn, [6]=We, [7]=be
    const float* efeats = (const float*)d_in[1];
    const int*   u      = (const int*)d_in[2];
    const int*   v      = (const int*)d_in[3];
    const float* Wn     = (const float*)d_in[4];
    const float* bn     = (const float*)d_in[5];
    const float* We     = (const float*)d_in[6];
    const float* be     = (const float*)d_in[7];

    float* out      = (float*)d_out;
    float* h_out    = out;                               // [N,64]
    float* edge_out = out + (size_t)N_NODES * 64;        // [E,64]

    void* accp = nullptr; cudaGetSymbolAddress(&accp, g_acc);
    void* degp = nullptr; cudaGetSymbolAddress(&degp, g_deg);
    cudaMemsetAsync(accp, 0, sizeof(float) * 2 * N_NODES * D, 0);
    cudaMemsetAsync(degp, 0, sizeof(float) * 2 * N_NODES, 0);

    scatter_kernel<<<(E_EDGES * 16) / 256, 256>>>((const float4*)efeats, u, v);

    int node_smem = 2 * 128 * PITCH * (int)sizeof(float);  // 69632 B
    cudaFuncSetAttribute(node_kernel, cudaFuncAttributeMaxDynamicSharedMemorySize, node_smem);
    node_kernel<<<(N_NODES + 63) / 64, 256, node_smem>>>(Wn, bn, We, be, h_out);

    cudaFuncSetAttribute(edge_kernel, cudaFuncAttributeMaxDynamicSharedMemorySize, SM_EDGE_BYTES);
    edge_kernel<<<E_EDGES / 128, 256, SM_EDGE_BYTES>>>(efeats, u, We, edge_out);
}

// round 10
// speedup vs baseline: 1.4131x; 1.0451x over previous
#include <cuda_runtime.h>
#include <cuda_bf16.h>
#include <cstdint>

#define N_NODES 100000
#define E_EDGES 1600000
#define D 64
#define EPA 72       // bf16 row pitch for K=64 tiles (144 B)
#define EPN 136      // bf16 row pitch for K=128 tiles (272 B)

// Scratch (device globals — no dynamic allocation allowed)
__device__ float g_acc[2 * N_NODES * D];   // [v-sums | u-sums]
__device__ float g_deg[2 * N_NODES];       // [deg_v | deg_u]
__device__ float g_hweb[N_NODES * D];      // h @ We_h^T + be

extern __shared__ char smem_raw[];

// ---------------------------------------------------------------------------
// shared mma/ldmatrix/split helpers
// ---------------------------------------------------------------------------
__device__ __forceinline__ void mma_bf16(float c[4], const unsigned a[4], const unsigned b[2]) {
    asm volatile(
        "mma.sync.aligned.m16n8k16.row.col.f32.bf16.bf16.f32 "
        "{%0,%1,%2,%3}, {%4,%5,%6,%7}, {%8,%9}, {%0,%1,%2,%3};"
        : "+f"(c[0]), "+f"(c[1]), "+f"(c[2]), "+f"(c[3])
        : "r"(a[0]), "r"(a[1]), "r"(a[2]), "r"(a[3]), "r"(b[0]), "r"(b[1]));
}
__device__ __forceinline__ void ldsm_x4(unsigned r[4], uint32_t addr) {
    asm volatile("ldmatrix.sync.aligned.m8n8.x4.shared.b16 {%0,%1,%2,%3}, [%4];"
                 : "=r"(r[0]), "=r"(r[1]), "=r"(r[2]), "=r"(r[3]) : "r"(addr));
}
__device__ __forceinline__ void ldsm_x2(unsigned r[2], uint32_t addr) {
    asm volatile("ldmatrix.sync.aligned.m8n8.x2.shared.b16 {%0,%1}, [%2];"
                 : "=r"(r[0]), "=r"(r[1]) : "r"(addr));
}
__device__ __forceinline__ unsigned pack_hi(float x, float y) {
    __nv_bfloat162 h(__float2bfloat16_rn(x), __float2bfloat16_rn(y));
    return *(unsigned*)&h;
}
__device__ __forceinline__ unsigned pack_lo(float x, float y) {
    __nv_bfloat16 hx = __float2bfloat16_rn(x), hy = __float2bfloat16_rn(y);
    __nv_bfloat162 l(__float2bfloat16_rn(x - __bfloat162float(hx)),
                     __float2bfloat16_rn(y - __bfloat162float(hy)));
    return *(unsigned*)&l;
}
static __device__ __forceinline__ uint32_t smem_u32e(const void* p) {
    uint32_t a;
    asm("{ .reg .u64 t; cvta.to.shared.u64 t, %1; cvt.u32.u64 %0, t; }" : "=r"(a) : "l"(p));
    return a;
}

// ---------------------------------------------------------------------------
// Stage 1: scatter-add efeats into per-node sums (both directions) + degrees
// ---------------------------------------------------------------------------
__device__ __forceinline__ void red_add_v4(float* p, float4 f) {
    asm volatile("red.global.add.v4.f32 [%0], {%1,%2,%3,%4};"
                 :: "l"(p), "f"(f.x), "f"(f.y), "f"(f.z), "f"(f.w) : "memory");
}

__global__ void scatter_kernel(const float4* __restrict__ ef4,
                               const int* __restrict__ u,
                               const int* __restrict__ v) {
    int idx = blockIdx.x * blockDim.x + threadIdx.x;  // exactly E*16
    int e = idx >> 4;
    int c = idx & 15;
    float4 f = ef4[idx];
    int vv = v[e];
    int uu = u[e];
    red_add_v4(&g_acc[(vv << 6) + (c << 2)], f);
    red_add_v4(&g_acc[(N_NODES << 6) + (uu << 6) + (c << 2)], f);
    if (c == 0) {
        atomicAdd(&g_deg[vv], 1.0f);
        atomicAdd(&g_deg[N_NODES + uu], 1.0f);
    }
}

// ---------------------------------------------------------------------------
// Stage 2 (mma): per-node — means, h = relu(cat @ Wn^T + bn), hweb = h@We_h^T+be
// 256 threads, 128-node tile; GEMM1 K=128 (pitch EPN), GEMM2 K=64 (pitch EPA).
// ---------------------------------------------------------------------------
// smem element offsets (bf16 units)
#define N_A1HI 0
#define N_A1LO (128 * EPN)                  // 17408
#define N_B1HI (2 * 128 * EPN)              // 34816
#define N_B1LO (2 * 128 * EPN + 64 * EPN)   // 43520
#define N_ELEMS (2 * 128 * EPN + 2 * 64 * EPN)  // 52224
#define N_SMEM_BYTES (N_ELEMS * 2)          // 104448
// GEMM2 buffers alias the A1 region (valid after post-mainloop sync)
#define N_A2HI 0
#define N_A2LO (128 * EPA)                  // 9216
#define N_B2HI (2 * 128 * EPA)              // 18432
#define N_B2LO (2 * 128 * EPA + 64 * EPA)   // 23040  (ends 27648 < 34816 ok)

__global__ void __launch_bounds__(256, 2)
node_kernel(const float* __restrict__ Wn,
            const float* __restrict__ bn,
            const float* __restrict__ We,
            const float* __restrict__ be,
            float* __restrict__ h_out) {
    __nv_bfloat16* bs = (__nv_bfloat16*)smem_raw;
    int t = threadIdx.x;
    int nb = blockIdx.x * 128;

    // ---- A1 fill: row = node, k<64 = mean_v, k>=64 = mean_u; bf16 hi/lo
    {
        int row = t >> 1, half = t & 1;
        int n = nb + row;
        bool ok = (n < N_NODES);
        float s = 0.f;
        const float4* src = (const float4*)g_acc;
        if (half == 0) { if (ok) s = 1.0f / fmaxf(g_deg[n], 1.0f); src += (size_t)n * 16; }
        else           { if (ok) s = 1.0f / fmaxf(g_deg[N_NODES + n], 1.0f); src += (size_t)(N_NODES + n) * 16; }
        unsigned* dh = (unsigned*)&bs[N_A1HI + row * EPN + half * 64];
        unsigned* dl = (unsigned*)&bs[N_A1LO + row * EPN + half * 64];
#pragma unroll
        for (int i = 0; i < 16; i++) {
            float4 f = ok ? src[i] : make_float4(0.f, 0.f, 0.f, 0.f);
            f.x *= s; f.y *= s; f.z *= s; f.w *= s;
            dh[i * 2 + 0] = pack_hi(f.x, f.y);
            dh[i * 2 + 1] = pack_hi(f.z, f.w);
            dl[i * 2 + 0] = pack_lo(f.x, f.y);
            dl[i * 2 + 1] = pack_lo(f.z, f.w);
        }
    }
    // ---- B1 fill: Wn [64][128]; 4 threads per row, 32 cols (8 float4) each
    {
        int o = t >> 2, q = t & 3;
        const float4* src = (const float4*)Wn + o * 32 + q * 8;
        unsigned* dh = (unsigned*)&bs[N_B1HI + o * EPN + q * 32];
        unsigned* dl = (unsigned*)&bs[N_B1LO + o * EPN + q * 32];
#pragma unroll
        for (int i = 0; i < 8; i++) {
            float4 f = src[i];
            dh[i * 2 + 0] = pack_hi(f.x, f.y);
            dh[i * 2 + 1] = pack_hi(f.z, f.w);
            dl[i * 2 + 0] = pack_lo(f.x, f.y);
            dl[i * 2 + 1] = pack_lo(f.z, f.w);
        }
    }
    __syncthreads();

    int wid = t >> 5, lane = t & 31;
    int wm = wid & 3, wn = wid >> 2;
    int g = lane >> 2, tg = lane & 3;

    int a_row_off = lane & 15;
    int a_col_off = (lane >> 4) << 3;
    int b_lane = lane & 15;
    int b_row_off = (b_lane < 8) ? b_lane : (b_lane - 8);
    int b_col_off = (b_lane < 8) ? 0 : 8;

    float c[2][4][4] = {};
    {
        uint32_t ahi = smem_u32e(&bs[N_A1HI + (wm * 32 + a_row_off) * EPN + a_col_off]);
        uint32_t alo = smem_u32e(&bs[N_A1LO + (wm * 32 + a_row_off) * EPN + a_col_off]);
        uint32_t bhi = smem_u32e(&bs[N_B1HI + (wn * 32 + b_row_off) * EPN + b_col_off]);
        uint32_t blo = smem_u32e(&bs[N_B1LO + (wn * 32 + b_row_off) * EPN + b_col_off]);
#pragma unroll
        for (int ks = 0; ks < 8; ks++) {
            uint32_t kb = ks * 32;
            unsigned ah[2][4], al[2][4];
            ldsm_x4(ah[0], ahi + kb);
            ldsm_x4(ah[1], ahi + kb + 16 * EPN * 2);
            ldsm_x4(al[0], alo + kb);
            ldsm_x4(al[1], alo + kb + 16 * EPN * 2);
            unsigned bh[4][2], bl[4][2];
#pragma unroll
            for (int nt = 0; nt < 4; nt++) {
                ldsm_x2(bh[nt], bhi + kb + nt * 8 * EPN * 2);
                ldsm_x2(bl[nt], blo + kb + nt * 8 * EPN * 2);
            }
#pragma unroll
            for (int mt = 0; mt < 2; mt++)
#pragma unroll
                for (int nt = 0; nt < 4; nt++) {
                    mma_bf16(c[mt][nt], ah[mt], bh[nt]);
                    mma_bf16(c[mt][nt], ah[mt], bl[nt]);
                    mma_bf16(c[mt][nt], al[mt], bh[nt]);
                }
        }
    }
    __syncthreads();   // all GEMM1 smem reads done; region reusable

    // ---- epilogue1: relu(+bn), write h, store A2 (bf16 split of h)
#pragma unroll
    for (int mt = 0; mt < 2; mt++) {
        int r0 = wm * 32 + mt * 16 + g;
        int r1 = r0 + 8;
#pragma unroll
        for (int nt = 0; nt < 4; nt++) {
            int col = wn * 32 + nt * 8 + 2 * tg;
            float2 bnv = *(const float2*)&bn[col];
            float v00 = fmaxf(c[mt][nt][0] + bnv.x, 0.f);
            float v01 = fmaxf(c[mt][nt][1] + bnv.y, 0.f);
            float v10 = fmaxf(c[mt][nt][2] + bnv.x, 0.f);
            float v11 = fmaxf(c[mt][nt][3] + bnv.y, 0.f);
            *(unsigned*)&bs[N_A2HI + r0 * EPA + col] = pack_hi(v00, v01);
            *(unsigned*)&bs[N_A2LO + r0 * EPA + col] = pack_lo(v00, v01);
            *(unsigned*)&bs[N_A2HI + r1 * EPA + col] = pack_hi(v10, v11);
            *(unsigned*)&bs[N_A2LO + r1 * EPA + col] = pack_lo(v10, v11);
            if (nb + r0 < N_NODES)
                *(float2*)&h_out[(size_t)(nb + r0) * 64 + col] = make_float2(v00, v01);
            if (nb + r1 < N_NODES)
                *(float2*)&h_out[(size_t)(nb + r1) * 64 + col] = make_float2(v10, v11);
        }
    }
    // ---- B2 fill: We_h = We[:, 0:64]; 4 threads per row, 16 cols each
    {
        int o = t >> 2, q = t & 3;
        const float4* src = (const float4*)We + o * 32 + q * 4;
        unsigned* dh = (unsigned*)&bs[N_B2HI + o * EPA + q * 16];
        unsigned* dl = (unsigned*)&bs[N_B2LO + o * EPA + q * 16];
#pragma unroll
        for (int i = 0; i < 4; i++) {
            float4 f = src[i];
            dh[i * 2 + 0] = pack_hi(f.x, f.y);
            dh[i * 2 + 1] = pack_hi(f.z, f.w);
            dl[i * 2 + 0] = pack_lo(f.x, f.y);
            dl[i * 2 + 1] = pack_lo(f.z, f.w);
        }
    }
    __syncthreads();

    // ---- GEMM2: hweb = h @ We_h^T (+be), K=64
    float c2[2][4][4] = {};
    {
        uint32_t ahi = smem_u32e(&bs[N_A2HI + (wm * 32 + a_row_off) * EPA + a_col_off]);
        uint32_t alo = smem_u32e(&bs[N_A2LO + (wm * 32 + a_row_off) * EPA + a_col_off]);
        uint32_t bhi = smem_u32e(&bs[N_B2HI + (wn * 32 + b_row_off) * EPA + b_col_off]);
        uint32_t blo = smem_u32e(&bs[N_B2LO + (wn * 32 + b_row_off) * EPA + b_col_off]);
#pragma unroll
        for (int ks = 0; ks < 4; ks++) {
            uint32_t kb = ks * 32;
            unsigned ah[2][4], al[2][4];
            ldsm_x4(ah[0], ahi + kb);
            ldsm_x4(ah[1], ahi + kb + 16 * EPA * 2);
            ldsm_x4(al[0], alo + kb);
            ldsm_x4(al[1], alo + kb + 16 * EPA * 2);
            unsigned bh[4][2], bl[4][2];
#pragma unroll
            for (int nt = 0; nt < 4; nt++) {
                ldsm_x2(bh[nt], bhi + kb + nt * 8 * EPA * 2);
                ldsm_x2(bl[nt], blo + kb + nt * 8 * EPA * 2);
            }
#pragma unroll
            for (int mt = 0; mt < 2; mt++)
#pragma unroll
                for (int nt = 0; nt < 4; nt++) {
                    mma_bf16(c2[mt][nt], ah[mt], bh[nt]);
                    mma_bf16(c2[mt][nt], ah[mt], bl[nt]);
                    mma_bf16(c2[mt][nt], al[mt], bh[nt]);
                }
        }
    }

    // ---- epilogue2: +be, write hweb
#pragma unroll
    for (int mt = 0; mt < 2; mt++) {
        int r0 = wm * 32 + mt * 16 + g;
        int r1 = r0 + 8;
#pragma unroll
        for (int nt = 0; nt < 4; nt++) {
            int col = wn * 32 + nt * 8 + 2 * tg;
            float2 bev = *(const float2*)&be[col];
            if (nb + r0 < N_NODES)
                *(float2*)&g_hweb[(size_t)(nb + r0) * 64 + col] =
                    make_float2(c2[mt][nt][0] + bev.x, c2[mt][nt][1] + bev.y);
            if (nb + r1 < N_NODES)
                *(float2*)&g_hweb[(size_t)(nb + r1) * 64 + col] =
                    make_float2(c2[mt][nt][2] + bev.x, c2[mt][nt][3] + bev.y);
        }
    }
}

// ---------------------------------------------------------------------------
// Stage 3: edge = hweb[u[e]] + efeats[e] @ We_e^T   (bf16x3 legacy mma)
// (unchanged from R8: 570us best)
// ---------------------------------------------------------------------------
#define SM_AHI 0
#define SM_ALO (128 * EPA)
#define SM_BHI (2 * 128 * EPA)
#define SM_BLO (2 * 128 * EPA + 64 * EPA)
#define SM_U_OFF (2 * 128 * EPA + 2 * 64 * EPA)
#define SM_EDGE_BYTES (SM_U_OFF * 2 + 128 * 4)

__global__ void __launch_bounds__(256, 3)
edge_kernel(const float* __restrict__ efeats,
            const int* __restrict__ u,
            const float* __restrict__ We,
            float* __restrict__ edge_out) {
    __nv_bfloat16* bs = (__nv_bfloat16*)smem_raw;
    __nv_bfloat16* A_hi = bs + SM_AHI;
    __nv_bfloat16* A_lo = bs + SM_ALO;
    __nv_bfloat16* B_hi = bs + SM_BHI;
    __nv_bfloat16* B_lo = bs + SM_BLO;
    int* u_s = (int*)(bs + SM_U_OFF);

    int t = threadIdx.x;
    int eb = blockIdx.x * 128;

    if (t < 128) u_s[t] = u[eb + t];

    {
        int row = t >> 1, half = t & 1;
        const float4* src = (const float4*)efeats + (size_t)(eb + row) * 16 + half * 8;
        unsigned* dh = (unsigned*)&A_hi[row * EPA + half * 32];
        unsigned* dl = (unsigned*)&A_lo[row * EPA + half * 32];
#pragma unroll
        for (int i = 0; i < 8; i++) {
            float4 f = src[i];
            dh[i * 2 + 0] = pack_hi(f.x, f.y);
            dh[i * 2 + 1] = pack_hi(f.z, f.w);
            dl[i * 2 + 0] = pack_lo(f.x, f.y);
            dl[i * 2 + 1] = pack_lo(f.z, f.w);
        }
    }
    {
        int o = t >> 2, q = t & 3;
        const float4* src = (const float4*)We + o * 32 + 16 + q * 4;
        unsigned* dh = (unsigned*)&B_hi[o * EPA + q * 16];
        unsigned* dl = (unsigned*)&B_lo[o * EPA + q * 16];
#pragma unroll
        for (int i = 0; i < 4; i++) {
            float4 f = src[i];
            dh[i * 2 + 0] = pack_hi(f.x, f.y);
            dh[i * 2 + 1] = pack_hi(f.z, f.w);
            dl[i * 2 + 0] = pack_lo(f.x, f.y);
            dl[i * 2 + 1] = pack_lo(f.z, f.w);
        }
    }
    __syncthreads();

    int wid = t >> 5, lane = t & 31;
    int wm = wid & 3, wn = wid >> 2;
    int g = lane >> 2, tg = lane & 3;

    int a_row_off = lane & 15;
    int a_col_off = (lane >> 4) << 3;
    uint32_t ahi_base = smem_u32e(&A_hi[(wm * 32 + a_row_off) * EPA + a_col_off]);
    uint32_t alo_base = smem_u32e(&A_lo[(wm * 32 + a_row_off) * EPA + a_col_off]);
    int b_lane = lane & 15;
    int b_row_off = (b_lane < 8) ? b_lane : (b_lane - 8);
    int b_col_off = (b_lane < 8) ? 0 : 8;
    uint32_t bhi_base = smem_u32e(&B_hi[(wn * 32 + b_row_off) * EPA + b_col_off]);
    uint32_t blo_base = smem_u32e(&B_lo[(wn * 32 + b_row_off) * EPA + b_col_off]);

    float c[2][4][4] = {};

#pragma unroll
    for (int ks = 0; ks < 4; ks++) {
        uint32_t kb = ks * 32;
        unsigned ah[2][4], al[2][4];
        ldsm_x4(ah[0], ahi_base + kb);
        ldsm_x4(ah[1], ahi_base + kb + 16 * EPA * 2);
        ldsm_x4(al[0], alo_base + kb);
        ldsm_x4(al[1], alo_base + kb + 16 * EPA * 2);
        unsigned bh[4][2], bl[4][2];
#pragma unroll
        for (int nt = 0; nt < 4; nt++) {
            ldsm_x2(bh[nt], bhi_base + kb + nt * 8 * EPA * 2);
            ldsm_x2(bl[nt], blo_base + kb + nt * 8 * EPA * 2);
        }
#pragma unroll
        for (int mt = 0; mt < 2; mt++)
#pragma unroll
            for (int nt = 0; nt < 4; nt++) {
                mma_bf16(c[mt][nt], ah[mt], bh[nt]);
                mma_bf16(c[mt][nt], ah[mt], bl[nt]);
                mma_bf16(c[mt][nt], al[mt], bh[nt]);
            }
    }

#pragma unroll
    for (int mt = 0; mt < 2; mt++) {
        int r0 = wm * 32 + mt * 16 + g;
        int r1 = r0 + 8;
        int u0 = u_s[r0], u1 = u_s[r1];
        size_t e0 = (size_t)(eb + r0), e1 = (size_t)(eb + r1);
#pragma unroll
        for (int nt = 0; nt < 4; nt++) {
            int col = wn * 32 + nt * 8 + 2 * tg;
            float2 g0 = *(const float2*)&g_hweb[u0 * 64 + col];
            float2 g1 = *(const float2*)&g_hweb[u1 * 64 + col];
            *(float2*)&edge_out[e0 * 64 + col] =
                make_float2(c[mt][nt][0] + g0.x, c[mt][nt][1] + g0.y);
            *(float2*)&edge_out[e1 * 64 + col] =
                make_float2(c[mt][nt][2] + g1.x, c[mt][nt][3] + g1.y);
        }
    }
}

// ---------------------------------------------------------------------------
extern "C" void kernel_launch(void* const* d_in, const int* in_sizes, int n_in,
                              void* d_out, int out_size) {
    // inputs: [0]=nfeats (unused), [1]=efeats, [2]=u, [3]=v, [4]=Wn, [5]=bn, [6]=We, [7]=be
    const float* efeats = (const float*)d_in[1];
    const int*   u      = (const int*)d_in[2];
    const int*   v      = (const int*)d_in[3];
    const float* Wn     = (const float*)d_in[4];
    const float* bn     = (const float*)d_in[5];
    const float* We     = (const float*)d_in[6];
    const float* be     = (const float*)d_in[7];

    float* out      = (float*)d_out;
    float* h_out    = out;                               // [N,64]
    float* edge_out = out + (size_t)N_NODES * 64;        // [E,64]

    void* accp = nullptr; cudaGetSymbolAddress(&accp, g_acc);
    void* degp = nullptr; cudaGetSymbolAddress(&degp, g_deg);
    cudaMemsetAsync(accp, 0, sizeof(float) * 2 * N_NODES * D, 0);
    cudaMemsetAsync(degp, 0, sizeof(float) * 2 * N_NODES, 0);

    scatter_kernel<<<(E_EDGES * 16) / 256, 256>>>((const float4*)efeats, u, v);

    cudaFuncSetAttribute(node_kernel, cudaFuncAttributeMaxDynamicSharedMemorySize, N_SMEM_BYTES);
    node_kernel<<<(N_NODES + 127) / 128, 256, N_SMEM_BYTES>>>(Wn, bn, We, be, h_out);

    cudaFuncSetAttribute(edge_kernel, cudaFuncAttributeMaxDynamicSharedMemorySize, SM_EDGE_BYTES);
    edge_kernel<<<E_EDGES / 128, 256, SM_EDGE_BYTES>>>(efeats, u, We, edge_out);
}

// round 11
// speedup vs baseline: 1.4153x; 1.0015x over previous
#include <cuda_runtime.h>
#include <cuda_bf16.h>
#include <cstdint>

#define N_NODES 100000
#define E_EDGES 1600000
#define D 64
#define EPA 72       // bf16 row pitch for K=64 tiles (144 B)
#define EPN 136      // bf16 row pitch for K=128 tiles (272 B)

// Scratch (device globals — no dynamic allocation allowed)
__device__ float g_acc[2 * N_NODES * D];   // [v-sums | u-sums]
__device__ float g_deg[2 * N_NODES];       // [deg_v | deg_u]
__device__ float g_hweb[N_NODES * D];      // h @ We_h^T + be

extern __shared__ char smem_raw[];

// ---------------------------------------------------------------------------
// shared helpers
// ---------------------------------------------------------------------------
__device__ __forceinline__ void mma_bf16(float c[4], const unsigned a[4], const unsigned b[2]) {
    asm volatile(
        "mma.sync.aligned.m16n8k16.row.col.f32.bf16.bf16.f32 "
        "{%0,%1,%2,%3}, {%4,%5,%6,%7}, {%8,%9}, {%0,%1,%2,%3};"
        : "+f"(c[0]), "+f"(c[1]), "+f"(c[2]), "+f"(c[3])
        : "r"(a[0]), "r"(a[1]), "r"(a[2]), "r"(a[3]), "r"(b[0]), "r"(b[1]));
}
__device__ __forceinline__ void ldsm_x4(unsigned r[4], uint32_t addr) {
    asm volatile("ldmatrix.sync.aligned.m8n8.x4.shared.b16 {%0,%1,%2,%3}, [%4];"
                 : "=r"(r[0]), "=r"(r[1]), "=r"(r[2]), "=r"(r[3]) : "r"(addr));
}
__device__ __forceinline__ void ldsm_x2(unsigned r[2], uint32_t addr) {
    asm volatile("ldmatrix.sync.aligned.m8n8.x2.shared.b16 {%0,%1}, [%2];"
                 : "=r"(r[0]), "=r"(r[1]) : "r"(addr));
}
__device__ __forceinline__ unsigned pack_hi(float x, float y) {
    __nv_bfloat162 h(__float2bfloat16_rn(x), __float2bfloat16_rn(y));
    return *(unsigned*)&h;
}
__device__ __forceinline__ unsigned pack_lo(float x, float y) {
    __nv_bfloat16 hx = __float2bfloat16_rn(x), hy = __float2bfloat16_rn(y);
    __nv_bfloat162 l(__float2bfloat16_rn(x - __bfloat162float(hx)),
                     __float2bfloat16_rn(y - __bfloat162float(hy)));
    return *(unsigned*)&l;
}
static __device__ __forceinline__ uint32_t smem_u32e(const void* p) {
    uint32_t a;
    asm("{ .reg .u64 t; cvta.to.shared.u64 t, %1; cvt.u32.u64 %0, t; }" : "=r"(a) : "l"(p));
    return a;
}
__device__ __forceinline__ float4 ldg_cs4(const float4* p) {
    float4 f;
    asm volatile("ld.global.cs.v4.f32 {%0,%1,%2,%3}, [%4];"
                 : "=f"(f.x), "=f"(f.y), "=f"(f.z), "=f"(f.w) : "l"(p));
    return f;
}
__device__ __forceinline__ void stg_cs2(float* p, float x, float y) {
    asm volatile("st.global.cs.v2.f32 [%0], {%1,%2};" :: "l"(p), "f"(x), "f"(y) : "memory");
}

// ---------------------------------------------------------------------------
// Stage 1: scatter-add efeats into per-node sums (both directions) + degrees
// efeats read with evict-first policy so g_acc stays L2-resident.
// ---------------------------------------------------------------------------
__device__ __forceinline__ void red_add_v4(float* p, float4 f) {
    asm volatile("red.global.add.v4.f32 [%0], {%1,%2,%3,%4};"
                 :: "l"(p), "f"(f.x), "f"(f.y), "f"(f.z), "f"(f.w) : "memory");
}

__global__ void scatter_kernel(const float4* __restrict__ ef4,
                               const int* __restrict__ u,
                               const int* __restrict__ v) {
    int idx = blockIdx.x * blockDim.x + threadIdx.x;  // exactly E*16
    int e = idx >> 4;
    int c = idx & 15;
    float4 f = ldg_cs4(ef4 + idx);
    int vv = v[e];
    int uu = u[e];
    red_add_v4(&g_acc[(vv << 6) + (c << 2)], f);
    red_add_v4(&g_acc[(N_NODES << 6) + (uu << 6) + (c << 2)], f);
    if (c == 0) {
        atomicAdd(&g_deg[vv], 1.0f);
        atomicAdd(&g_deg[N_NODES + uu], 1.0f);
    }
}

// ---------------------------------------------------------------------------
// Stage 2 (mma): per-node — means, h = relu(cat @ Wn^T + bn), hweb = h@We_h^T+be
// ---------------------------------------------------------------------------
#define N_A1HI 0
#define N_A1LO (128 * EPN)
#define N_B1HI (2 * 128 * EPN)
#define N_B1LO (2 * 128 * EPN + 64 * EPN)
#define N_ELEMS (2 * 128 * EPN + 2 * 64 * EPN)
#define N_SMEM_BYTES (N_ELEMS * 2)          // 104448
#define N_A2HI 0
#define N_A2LO (128 * EPA)
#define N_B2HI (2 * 128 * EPA)
#define N_B2LO (2 * 128 * EPA + 64 * EPA)

__global__ void __launch_bounds__(256, 2)
node_kernel(const float* __restrict__ Wn,
            const float* __restrict__ bn,
            const float* __restrict__ We,
            const float* __restrict__ be,
            float* __restrict__ h_out) {
    __nv_bfloat16* bs = (__nv_bfloat16*)smem_raw;
    int t = threadIdx.x;
    int nb = blockIdx.x * 128;

    {
        int row = t >> 1, half = t & 1;
        int n = nb + row;
        bool ok = (n < N_NODES);
        float s = 0.f;
        const float4* src = (const float4*)g_acc;
        if (half == 0) { if (ok) s = 1.0f / fmaxf(g_deg[n], 1.0f); src += (size_t)n * 16; }
        else           { if (ok) s = 1.0f / fmaxf(g_deg[N_NODES + n], 1.0f); src += (size_t)(N_NODES + n) * 16; }
        unsigned* dh = (unsigned*)&bs[N_A1HI + row * EPN + half * 64];
        unsigned* dl = (unsigned*)&bs[N_A1LO + row * EPN + half * 64];
#pragma unroll
        for (int i = 0; i < 16; i++) {
            float4 f = ok ? src[i] : make_float4(0.f, 0.f, 0.f, 0.f);
            f.x *= s; f.y *= s; f.z *= s; f.w *= s;
            dh[i * 2 + 0] = pack_hi(f.x, f.y);
            dh[i * 2 + 1] = pack_hi(f.z, f.w);
            dl[i * 2 + 0] = pack_lo(f.x, f.y);
            dl[i * 2 + 1] = pack_lo(f.z, f.w);
        }
    }
    {
        int o = t >> 2, q = t & 3;
        const float4* src = (const float4*)Wn + o * 32 + q * 8;
        unsigned* dh = (unsigned*)&bs[N_B1HI + o * EPN + q * 32];
        unsigned* dl = (unsigned*)&bs[N_B1LO + o * EPN + q * 32];
#pragma unroll
        for (int i = 0; i < 8; i++) {
            float4 f = src[i];
            dh[i * 2 + 0] = pack_hi(f.x, f.y);
            dh[i * 2 + 1] = pack_hi(f.z, f.w);
            dl[i * 2 + 0] = pack_lo(f.x, f.y);
            dl[i * 2 + 1] = pack_lo(f.z, f.w);
        }
    }
    __syncthreads();

    int wid = t >> 5, lane = t & 31;
    int wm = wid & 3, wn = wid >> 2;
    int g = lane >> 2, tg = lane & 3;

    int a_row_off = lane & 15;
    int a_col_off = (lane >> 4) << 3;
    int b_lane = lane & 15;
    int b_row_off = (b_lane < 8) ? b_lane : (b_lane - 8);
    int b_col_off = (b_lane < 8) ? 0 : 8;

    float c[2][4][4] = {};
    {
        uint32_t ahi = smem_u32e(&bs[N_A1HI + (wm * 32 + a_row_off) * EPN + a_col_off]);
        uint32_t alo = smem_u32e(&bs[N_A1LO + (wm * 32 + a_row_off) * EPN + a_col_off]);
        uint32_t bhi = smem_u32e(&bs[N_B1HI + (wn * 32 + b_row_off) * EPN + b_col_off]);
        uint32_t blo = smem_u32e(&bs[N_B1LO + (wn * 32 + b_row_off) * EPN + b_col_off]);
#pragma unroll
        for (int ks = 0; ks < 8; ks++) {
            uint32_t kb = ks * 32;
            unsigned ah[2][4], al[2][4];
            ldsm_x4(ah[0], ahi + kb);
            ldsm_x4(ah[1], ahi + kb + 16 * EPN * 2);
            ldsm_x4(al[0], alo + kb);
            ldsm_x4(al[1], alo + kb + 16 * EPN * 2);
            unsigned bh[4][2], bl[4][2];
#pragma unroll
            for (int nt = 0; nt < 4; nt++) {
                ldsm_x2(bh[nt], bhi + kb + nt * 8 * EPN * 2);
                ldsm_x2(bl[nt], blo + kb + nt * 8 * EPN * 2);
            }
#pragma unroll
            for (int mt = 0; mt < 2; mt++)
#pragma unroll
                for (int nt = 0; nt < 4; nt++) {
                    mma_bf16(c[mt][nt], ah[mt], bh[nt]);
                    mma_bf16(c[mt][nt], ah[mt], bl[nt]);
                    mma_bf16(c[mt][nt], al[mt], bh[nt]);
                }
        }
    }
    __syncthreads();

    // epilogue1: relu(+bn), write h (streaming), store A2 split of h
#pragma unroll
    for (int mt = 0; mt < 2; mt++) {
        int r0 = wm * 32 + mt * 16 + g;
        int r1 = r0 + 8;
#pragma unroll
        for (int nt = 0; nt < 4; nt++) {
            int col = wn * 32 + nt * 8 + 2 * tg;
            float2 bnv = *(const float2*)&bn[col];
            float v00 = fmaxf(c[mt][nt][0] + bnv.x, 0.f);
            float v01 = fmaxf(c[mt][nt][1] + bnv.y, 0.f);
            float v10 = fmaxf(c[mt][nt][2] + bnv.x, 0.f);
            float v11 = fmaxf(c[mt][nt][3] + bnv.y, 0.f);
            *(unsigned*)&bs[N_A2HI + r0 * EPA + col] = pack_hi(v00, v01);
            *(unsigned*)&bs[N_A2LO + r0 * EPA + col] = pack_lo(v00, v01);
            *(unsigned*)&bs[N_A2HI + r1 * EPA + col] = pack_hi(v10, v11);
            *(unsigned*)&bs[N_A2LO + r1 * EPA + col] = pack_lo(v10, v11);
            if (nb + r0 < N_NODES)
                stg_cs2(&h_out[(size_t)(nb + r0) * 64 + col], v00, v01);
            if (nb + r1 < N_NODES)
                stg_cs2(&h_out[(size_t)(nb + r1) * 64 + col], v10, v11);
        }
    }
    {
        int o = t >> 2, q = t & 3;
        const float4* src = (const float4*)We + o * 32 + q * 4;
        unsigned* dh = (unsigned*)&bs[N_B2HI + o * EPA + q * 16];
        unsigned* dl = (unsigned*)&bs[N_B2LO + o * EPA + q * 16];
#pragma unroll
        for (int i = 0; i < 4; i++) {
            float4 f = src[i];
            dh[i * 2 + 0] = pack_hi(f.x, f.y);
            dh[i * 2 + 1] = pack_hi(f.z, f.w);
            dl[i * 2 + 0] = pack_lo(f.x, f.y);
            dl[i * 2 + 1] = pack_lo(f.z, f.w);
        }
    }
    __syncthreads();

    float c2[2][4][4] = {};
    {
        uint32_t ahi = smem_u32e(&bs[N_A2HI + (wm * 32 + a_row_off) * EPA + a_col_off]);
        uint32_t alo = smem_u32e(&bs[N_A2LO + (wm * 32 + a_row_off) * EPA + a_col_off]);
        uint32_t bhi = smem_u32e(&bs[N_B2HI + (wn * 32 + b_row_off) * EPA + b_col_off]);
        uint32_t blo = smem_u32e(&bs[N_B2LO + (wn * 32 + b_row_off) * EPA + b_col_off]);
#pragma unroll
        for (int ks = 0; ks < 4; ks++) {
            uint32_t kb = ks * 32;
            unsigned ah[2][4], al[2][4];
            ldsm_x4(ah[0], ahi + kb);
            ldsm_x4(ah[1], ahi + kb + 16 * EPA * 2);
            ldsm_x4(al[0], alo + kb);
            ldsm_x4(al[1], alo + kb + 16 * EPA * 2);
            unsigned bh[4][2], bl[4][2];
#pragma unroll
            for (int nt = 0; nt < 4; nt++) {
                ldsm_x2(bh[nt], bhi + kb + nt * 8 * EPA * 2);
                ldsm_x2(bl[nt], blo + kb + nt * 8 * EPA * 2);
            }
#pragma unroll
            for (int mt = 0; mt < 2; mt++)
#pragma unroll
                for (int nt = 0; nt < 4; nt++) {
                    mma_bf16(c2[mt][nt], ah[mt], bh[nt]);
                    mma_bf16(c2[mt][nt], ah[mt], bl[nt]);
                    mma_bf16(c2[mt][nt], al[mt], bh[nt]);
                }
        }
    }

#pragma unroll
    for (int mt = 0; mt < 2; mt++) {
        int r0 = wm * 32 + mt * 16 + g;
        int r1 = r0 + 8;
#pragma unroll
        for (int nt = 0; nt < 4; nt++) {
            int col = wn * 32 + nt * 8 + 2 * tg;
            float2 bev = *(const float2*)&be[col];
            if (nb + r0 < N_NODES)
                *(float2*)&g_hweb[(size_t)(nb + r0) * 64 + col] =
                    make_float2(c2[mt][nt][0] + bev.x, c2[mt][nt][1] + bev.y);
            if (nb + r1 < N_NODES)
                *(float2*)&g_hweb[(size_t)(nb + r1) * 64 + col] =
                    make_float2(c2[mt][nt][2] + bev.x, c2[mt][nt][3] + bev.y);
        }
    }
}

// ---------------------------------------------------------------------------
// Stage 3: edge = hweb[u[e]] + efeats[e] @ We_e^T   (bf16x3 legacy mma)
// efeats read evict-first; edge_out stored evict-first (protect g_hweb in L2).
// ---------------------------------------------------------------------------
#define SM_AHI 0
#define SM_ALO (128 * EPA)
#define SM_BHI (2 * 128 * EPA)
#define SM_BLO (2 * 128 * EPA + 64 * EPA)
#define SM_U_OFF (2 * 128 * EPA + 2 * 64 * EPA)
#define SM_EDGE_BYTES (SM_U_OFF * 2 + 128 * 4)

__global__ void __launch_bounds__(256, 3)
edge_kernel(const float* __restrict__ efeats,
            const int* __restrict__ u,
            const float* __restrict__ We,
            float* __restrict__ edge_out) {
    __nv_bfloat16* bs = (__nv_bfloat16*)smem_raw;
    __nv_bfloat16* A_hi = bs + SM_AHI;
    __nv_bfloat16* A_lo = bs + SM_ALO;
    __nv_bfloat16* B_hi = bs + SM_BHI;
    __nv_bfloat16* B_lo = bs + SM_BLO;
    int* u_s = (int*)(bs + SM_U_OFF);

    int t = threadIdx.x;
    int eb = blockIdx.x * 128;

    if (t < 128) u_s[t] = u[eb + t];

    {
        int row = t >> 1, half = t & 1;
        const float4* src = (const float4*)efeats + (size_t)(eb + row) * 16 + half * 8;
        unsigned* dh = (unsigned*)&A_hi[row * EPA + half * 32];
        unsigned* dl = (unsigned*)&A_lo[row * EPA + half * 32];
#pragma unroll
        for (int i = 0; i < 8; i++) {
            float4 f = ldg_cs4(src + i);
            dh[i * 2 + 0] = pack_hi(f.x, f.y);
            dh[i * 2 + 1] = pack_hi(f.z, f.w);
            dl[i * 2 + 0] = pack_lo(f.x, f.y);
            dl[i * 2 + 1] = pack_lo(f.z, f.w);
        }
    }
    {
        int o = t >> 2, q = t & 3;
        const float4* src = (const float4*)We + o * 32 + 16 + q * 4;
        unsigned* dh = (unsigned*)&B_hi[o * EPA + q * 16];
        unsigned* dl = (unsigned*)&B_lo[o * EPA + q * 16];
#pragma unroll
        for (int i = 0; i < 4; i++) {
            float4 f = src[i];
            dh[i * 2 + 0] = pack_hi(f.x, f.y);
            dh[i * 2 + 1] = pack_hi(f.z, f.w);
            dl[i * 2 + 0] = pack_lo(f.x, f.y);
            dl[i * 2 + 1] = pack_lo(f.z, f.w);
        }
    }
    __syncthreads();

    int wid = t >> 5, lane = t & 31;
    int wm = wid & 3, wn = wid >> 2;
    int g = lane >> 2, tg = lane & 3;

    int a_row_off = lane & 15;
    int a_col_off = (lane >> 4) << 3;
    uint32_t ahi_base = smem_u32e(&A_hi[(wm * 32 + a_row_off) * EPA + a_col_off]);
    uint32_t alo_base = smem_u32e(&A_lo[(wm * 32 + a_row_off) * EPA + a_col_off]);
    int b_lane = lane & 15;
    int b_row_off = (b_lane < 8) ? b_lane : (b_lane - 8);
    int b_col_off = (b_lane < 8) ? 0 : 8;
    uint32_t bhi_base = smem_u32e(&B_hi[(wn * 32 + b_row_off) * EPA + b_col_off]);
    uint32_t blo_base = smem_u32e(&B_lo[(wn * 32 + b_row_off) * EPA + b_col_off]);

    float c[2][4][4] = {};

#pragma unroll
    for (int ks = 0; ks < 4; ks++) {
        uint32_t kb = ks * 32;
        unsigned ah[2][4], al[2][4];
        ldsm_x4(ah[0], ahi_base + kb);
        ldsm_x4(ah[1], ahi_base + kb + 16 * EPA * 2);
        ldsm_x4(al[0], alo_base + kb);
        ldsm_x4(al[1], alo_base + kb + 16 * EPA * 2);
        unsigned bh[4][2], bl[4][2];
#pragma unroll
        for (int nt = 0; nt < 4; nt++) {
            ldsm_x2(bh[nt], bhi_base + kb + nt * 8 * EPA * 2);
            ldsm_x2(bl[nt], blo_base + kb + nt * 8 * EPA * 2);
        }
#pragma unroll
        for (int mt = 0; mt < 2; mt++)
#pragma unroll
            for (int nt = 0; nt < 4; nt++) {
                mma_bf16(c[mt][nt], ah[mt], bh[nt]);
                mma_bf16(c[mt][nt], ah[mt], bl[nt]);
                mma_bf16(c[mt][nt], al[mt], bh[nt]);
            }
    }

#pragma unroll
    for (int mt = 0; mt < 2; mt++) {
        int r0 = wm * 32 + mt * 16 + g;
        int r1 = r0 + 8;
        int u0 = u_s[r0], u1 = u_s[r1];
        size_t e0 = (size_t)(eb + r0), e1 = (size_t)(eb + r1);
#pragma unroll
        for (int nt = 0; nt < 4; nt++) {
            int col = wn * 32 + nt * 8 + 2 * tg;
            float2 g0 = *(const float2*)&g_hweb[u0 * 64 + col];
            float2 g1 = *(const float2*)&g_hweb[u1 * 64 + col];
            stg_cs2(&edge_out[e0 * 64 + col], c[mt][nt][0] + g0.x, c[mt][nt][1] + g0.y);
            stg_cs2(&edge_out[e1 * 64 + col], c[mt][nt][2] + g1.x, c[mt][nt][3] + g1.y);
        }
    }
}

// ---------------------------------------------------------------------------
extern "C" void kernel_launch(void* const* d_in, const int* in_sizes, int n_in,
                              void* d_out, int out_size) {
    // inputs: [0]=nfeats (unused), [1]=efeats, [2]=u, [3]=v, [4]=Wn, [5]=bn, [6]=We, [7]=be
    const float* efeats = (const float*)d_in[1];
    const int*   u      = (const int*)d_in[2];
    const int*   v      = (const int*)d_in[3];
    const float* Wn     = (const float*)d_in[4];
    const float* bn     = (const float*)d_in[5];
    const float* We     = (const float*)d_in[6];
    const float* be     = (const float*)d_in[7];

    float* out      = (float*)d_out;
    float* h_out    = out;                               // [N,64]
    float* edge_out = out + (size_t)N_NODES * 64;        // [E,64]

    void* accp = nullptr; cudaGetSymbolAddress(&accp, g_acc);
    void* degp = nullptr; cudaGetSymbolAddress(&degp, g_deg);
    cudaMemsetAsync(accp, 0, sizeof(float) * 2 * N_NODES * D, 0);
    cudaMemsetAsync(degp, 0, sizeof(float) * 2 * N_NODES, 0);

    scatter_kernel<<<(E_EDGES * 16) / 256, 256>>>((const float4*)efeats, u, v);

    cudaFuncSetAttribute(node_kernel, cudaFuncAttributeMaxDynamicSharedMemorySize, N_SMEM_BYTES);
    node_kernel<<<(N_NODES + 127) / 128, 256, N_SMEM_BYTES>>>(Wn, bn, We, be, h_out);

    cudaFuncSetAttribute(edge_kernel, cudaFuncAttributeMaxDynamicSharedMemorySize, SM_EDGE_BYTES);
    edge_kernel<<<E_EDGES / 128, 256, SM_EDGE_BYTES>>>(efeats, u, We, edge_out);
}

// round 12
// speedup vs baseline: 1.4992x; 1.0593x over previous
#include <cuda_runtime.h>
#include <cuda_bf16.h>
#include <cstdint>

#define N_NODES 100000
#define E_EDGES 1600000
#define D 64
#define EPA 72       // bf16 row pitch for K=64 tiles (144 B)
#define EPN 136      // bf16 row pitch for K=128 tiles (272 B)

// Scratch (device globals — no dynamic allocation allowed)
__device__ float g_acc[2 * N_NODES * D];   // [v-sums | u-sums]
__device__ float g_deg[2 * N_NODES];       // [deg_v | deg_u]
__device__ float g_hweb[N_NODES * D];      // h @ We_h^T + be

extern __shared__ char smem_raw[];

// ---------------------------------------------------------------------------
// shared helpers
// ---------------------------------------------------------------------------
__device__ __forceinline__ void mma_bf16(float c[4], const unsigned a[4], const unsigned b[2]) {
    asm volatile(
        "mma.sync.aligned.m16n8k16.row.col.f32.bf16.bf16.f32 "
        "{%0,%1,%2,%3}, {%4,%5,%6,%7}, {%8,%9}, {%0,%1,%2,%3};"
        : "+f"(c[0]), "+f"(c[1]), "+f"(c[2]), "+f"(c[3])
        : "r"(a[0]), "r"(a[1]), "r"(a[2]), "r"(a[3]), "r"(b[0]), "r"(b[1]));
}
__device__ __forceinline__ void ldsm_x4(unsigned r[4], uint32_t addr) {
    asm volatile("ldmatrix.sync.aligned.m8n8.x4.shared.b16 {%0,%1,%2,%3}, [%4];"
                 : "=r"(r[0]), "=r"(r[1]), "=r"(r[2]), "=r"(r[3]) : "r"(addr));
}
__device__ __forceinline__ void ldsm_x2(unsigned r[2], uint32_t addr) {
    asm volatile("ldmatrix.sync.aligned.m8n8.x2.shared.b16 {%0,%1}, [%2];"
                 : "=r"(r[0]), "=r"(r[1]) : "r"(addr));
}
__device__ __forceinline__ unsigned pack_hi(float x, float y) {
    __nv_bfloat162 h(__float2bfloat16_rn(x), __float2bfloat16_rn(y));
    return *(unsigned*)&h;
}
__device__ __forceinline__ unsigned pack_lo(float x, float y) {
    __nv_bfloat16 hx = __float2bfloat16_rn(x), hy = __float2bfloat16_rn(y);
    __nv_bfloat162 l(__float2bfloat16_rn(x - __bfloat162float(hx)),
                     __float2bfloat16_rn(y - __bfloat162float(hy)));
    return *(unsigned*)&l;
}
static __device__ __forceinline__ uint32_t smem_u32e(const void* p) {
    uint32_t a;
    asm("{ .reg .u64 t; cvta.to.shared.u64 t, %1; cvt.u32.u64 %0, t; }" : "=r"(a) : "l"(p));
    return a;
}
// cache-policy ops WITHOUT compiler barriers (intrinsics, not asm volatile)
__device__ __forceinline__ float4 ldg_cs4(const float4* p) { return __ldcs(p); }
__device__ __forceinline__ void stg_cs2(float* p, float x, float y) {
    __stcs((float2*)p, make_float2(x, y));
}

// ---------------------------------------------------------------------------
// Stage 1: scatter-add efeats into per-node sums (both directions) + degrees
// (L2-atomic-bound at its floor; efeats read evict-first keeps g_acc resident)
// ---------------------------------------------------------------------------
__device__ __forceinline__ void red_add_v4(float* p, float4 f) {
    asm volatile("red.global.add.v4.f32 [%0], {%1,%2,%3,%4};"
                 :: "l"(p), "f"(f.x), "f"(f.y), "f"(f.z), "f"(f.w) : "memory");
}

__global__ void scatter_kernel(const float4* __restrict__ ef4,
                               const int* __restrict__ u,
                               const int* __restrict__ v) {
    int idx = blockIdx.x * blockDim.x + threadIdx.x;  // exactly E*16
    int e = idx >> 4;
    int c = idx & 15;
    float4 f = ldg_cs4(ef4 + idx);
    int vv = v[e];
    int uu = u[e];
    red_add_v4(&g_acc[(vv << 6) + (c << 2)], f);
    red_add_v4(&g_acc[(N_NODES << 6) + (uu << 6) + (c << 2)], f);
    if (c == 0) {
        atomicAdd(&g_deg[vv], 1.0f);
        atomicAdd(&g_deg[N_NODES + uu], 1.0f);
    }
}

// ---------------------------------------------------------------------------
// Stage 2 (mma): per-node — means, h = relu(cat @ Wn^T + bn), hweb = h@We_h^T+be
// ---------------------------------------------------------------------------
#define N_A1HI 0
#define N_A1LO (128 * EPN)
#define N_B1HI (2 * 128 * EPN)
#define N_B1LO (2 * 128 * EPN + 64 * EPN)
#define N_ELEMS (2 * 128 * EPN + 2 * 64 * EPN)
#define N_SMEM_BYTES (N_ELEMS * 2)          // 104448
#define N_A2HI 0
#define N_A2LO (128 * EPA)
#define N_B2HI (2 * 128 * EPA)
#define N_B2LO (2 * 128 * EPA + 64 * EPA)

__global__ void __launch_bounds__(256, 2)
node_kernel(const float* __restrict__ Wn,
            const float* __restrict__ bn,
            const float* __restrict__ We,
            const float* __restrict__ be,
            float* __restrict__ h_out) {
    __nv_bfloat16* bs = (__nv_bfloat16*)smem_raw;
    int t = threadIdx.x;
    int nb = blockIdx.x * 128;

    {
        int row = t >> 1, half = t & 1;
        int n = nb + row;
        bool ok = (n < N_NODES);
        float s = 0.f;
        const float4* src = (const float4*)g_acc;
        if (half == 0) { if (ok) s = 1.0f / fmaxf(g_deg[n], 1.0f); src += (size_t)n * 16; }
        else           { if (ok) s = 1.0f / fmaxf(g_deg[N_NODES + n], 1.0f); src += (size_t)(N_NODES + n) * 16; }
        unsigned* dh = (unsigned*)&bs[N_A1HI + row * EPN + half * 64];
        unsigned* dl = (unsigned*)&bs[N_A1LO + row * EPN + half * 64];
#pragma unroll
        for (int i = 0; i < 16; i++) {
            float4 f = ok ? src[i] : make_float4(0.f, 0.f, 0.f, 0.f);
            f.x *= s; f.y *= s; f.z *= s; f.w *= s;
            dh[i * 2 + 0] = pack_hi(f.x, f.y);
            dh[i * 2 + 1] = pack_hi(f.z, f.w);
            dl[i * 2 + 0] = pack_lo(f.x, f.y);
            dl[i * 2 + 1] = pack_lo(f.z, f.w);
        }
    }
    {
        int o = t >> 2, q = t & 3;
        const float4* src = (const float4*)Wn + o * 32 + q * 8;
        unsigned* dh = (unsigned*)&bs[N_B1HI + o * EPN + q * 32];
        unsigned* dl = (unsigned*)&bs[N_B1LO + o * EPN + q * 32];
#pragma unroll
        for (int i = 0; i < 8; i++) {
            float4 f = src[i];
            dh[i * 2 + 0] = pack_hi(f.x, f.y);
            dh[i * 2 + 1] = pack_hi(f.z, f.w);
            dl[i * 2 + 0] = pack_lo(f.x, f.y);
            dl[i * 2 + 1] = pack_lo(f.z, f.w);
        }
    }
    __syncthreads();

    int wid = t >> 5, lane = t & 31;
    int wm = wid & 3, wn = wid >> 2;
    int g = lane >> 2, tg = lane & 3;

    int a_row_off = lane & 15;
    int a_col_off = (lane >> 4) << 3;
    int b_lane = lane & 15;
    int b_row_off = (b_lane < 8) ? b_lane : (b_lane - 8);
    int b_col_off = (b_lane < 8) ? 0 : 8;

    float c[2][4][4] = {};
    {
        uint32_t ahi = smem_u32e(&bs[N_A1HI + (wm * 32 + a_row_off) * EPN + a_col_off]);
        uint32_t alo = smem_u32e(&bs[N_A1LO + (wm * 32 + a_row_off) * EPN + a_col_off]);
        uint32_t bhi = smem_u32e(&bs[N_B1HI + (wn * 32 + b_row_off) * EPN + b_col_off]);
        uint32_t blo = smem_u32e(&bs[N_B1LO + (wn * 32 + b_row_off) * EPN + b_col_off]);
#pragma unroll
        for (int ks = 0; ks < 8; ks++) {
            uint32_t kb = ks * 32;
            unsigned ah[2][4], al[2][4];
            ldsm_x4(ah[0], ahi + kb);
            ldsm_x4(ah[1], ahi + kb + 16 * EPN * 2);
            ldsm_x4(al[0], alo + kb);
            ldsm_x4(al[1], alo + kb + 16 * EPN * 2);
            unsigned bh[4][2], bl[4][2];
#pragma unroll
            for (int nt = 0; nt < 4; nt++) {
                ldsm_x2(bh[nt], bhi + kb + nt * 8 * EPN * 2);
                ldsm_x2(bl[nt], blo + kb + nt * 8 * EPN * 2);
            }
#pragma unroll
            for (int mt = 0; mt < 2; mt++)
#pragma unroll
                for (int nt = 0; nt < 4; nt++) {
                    mma_bf16(c[mt][nt], ah[mt], bh[nt]);
                    mma_bf16(c[mt][nt], ah[mt], bl[nt]);
                    mma_bf16(c[mt][nt], al[mt], bh[nt]);
                }
        }
    }
    __syncthreads();

    // epilogue1: relu(+bn), write h (streaming), store A2 split of h
#pragma unroll
    for (int mt = 0; mt < 2; mt++) {
        int r0 = wm * 32 + mt * 16 + g;
        int r1 = r0 + 8;
#pragma unroll
        for (int nt = 0; nt < 4; nt++) {
            int col = wn * 32 + nt * 8 + 2 * tg;
            float2 bnv = *(const float2*)&bn[col];
            float v00 = fmaxf(c[mt][nt][0] + bnv.x, 0.f);
            float v01 = fmaxf(c[mt][nt][1] + bnv.y, 0.f);
            float v10 = fmaxf(c[mt][nt][2] + bnv.x, 0.f);
            float v11 = fmaxf(c[mt][nt][3] + bnv.y, 0.f);
            *(unsigned*)&bs[N_A2HI + r0 * EPA + col] = pack_hi(v00, v01);
            *(unsigned*)&bs[N_A2LO + r0 * EPA + col] = pack_lo(v00, v01);
            *(unsigned*)&bs[N_A2HI + r1 * EPA + col] = pack_hi(v10, v11);
            *(unsigned*)&bs[N_A2LO + r1 * EPA + col] = pack_lo(v10, v11);
            if (nb + r0 < N_NODES)
                stg_cs2(&h_out[(size_t)(nb + r0) * 64 + col], v00, v01);
            if (nb + r1 < N_NODES)
                stg_cs2(&h_out[(size_t)(nb + r1) * 64 + col], v10, v11);
        }
    }
    {
        int o = t >> 2, q = t & 3;
        const float4* src = (const float4*)We + o * 32 + q * 4;
        unsigned* dh = (unsigned*)&bs[N_B2HI + o * EPA + q * 16];
        unsigned* dl = (unsigned*)&bs[N_B2LO + o * EPA + q * 16];
#pragma unroll
        for (int i = 0; i < 4; i++) {
            float4 f = src[i];
            dh[i * 2 + 0] = pack_hi(f.x, f.y);
            dh[i * 2 + 1] = pack_hi(f.z, f.w);
            dl[i * 2 + 0] = pack_lo(f.x, f.y);
            dl[i * 2 + 1] = pack_lo(f.z, f.w);
        }
    }
    __syncthreads();

    float c2[2][4][4] = {};
    {
        uint32_t ahi = smem_u32e(&bs[N_A2HI + (wm * 32 + a_row_off) * EPA + a_col_off]);
        uint32_t alo = smem_u32e(&bs[N_A2LO + (wm * 32 + a_row_off) * EPA + a_col_off]);
        uint32_t bhi = smem_u32e(&bs[N_B2HI + (wn * 32 + b_row_off) * EPA + b_col_off]);
        uint32_t blo = smem_u32e(&bs[N_B2LO + (wn * 32 + b_row_off) * EPA + b_col_off]);
#pragma unroll
        for (int ks = 0; ks < 4; ks++) {
            uint32_t kb = ks * 32;
            unsigned ah[2][4], al[2][4];
            ldsm_x4(ah[0], ahi + kb);
            ldsm_x4(ah[1], ahi + kb + 16 * EPA * 2);
            ldsm_x4(al[0], alo + kb);
            ldsm_x4(al[1], alo + kb + 16 * EPA * 2);
            unsigned bh[4][2], bl[4][2];
#pragma unroll
            for (int nt = 0; nt < 4; nt++) {
                ldsm_x2(bh[nt], bhi + kb + nt * 8 * EPA * 2);
                ldsm_x2(bl[nt], blo + kb + nt * 8 * EPA * 2);
            }
#pragma unroll
            for (int mt = 0; mt < 2; mt++)
#pragma unroll
                for (int nt = 0; nt < 4; nt++) {
                    mma_bf16(c2[mt][nt], ah[mt], bh[nt]);
                    mma_bf16(c2[mt][nt], ah[mt], bl[nt]);
                    mma_bf16(c2[mt][nt], al[mt], bh[nt]);
                }
        }
    }

#pragma unroll
    for (int mt = 0; mt < 2; mt++) {
        int r0 = wm * 32 + mt * 16 + g;
        int r1 = r0 + 8;
#pragma unroll
        for (int nt = 0; nt < 4; nt++) {
            int col = wn * 32 + nt * 8 + 2 * tg;
            float2 bev = *(const float2*)&be[col];
            if (nb + r0 < N_NODES)
                *(float2*)&g_hweb[(size_t)(nb + r0) * 64 + col] =
                    make_float2(c2[mt][nt][0] + bev.x, c2[mt][nt][1] + bev.y);
            if (nb + r1 < N_NODES)
                *(float2*)&g_hweb[(size_t)(nb + r1) * 64 + col] =
                    make_float2(c2[mt][nt][2] + bev.x, c2[mt][nt][3] + bev.y);
        }
    }
}

// ---------------------------------------------------------------------------
// Stage 3: edge = hweb[u[e]] + efeats[e] @ We_e^T   (bf16x3 legacy mma)
// Epilogue batches all 16 gather loads before any store (MLP 16).
// ---------------------------------------------------------------------------
#define SM_AHI 0
#define SM_ALO (128 * EPA)
#define SM_BHI (2 * 128 * EPA)
#define SM_BLO (2 * 128 * EPA + 64 * EPA)
#define SM_U_OFF (2 * 128 * EPA + 2 * 64 * EPA)
#define SM_EDGE_BYTES (SM_U_OFF * 2 + 128 * 4)

__global__ void __launch_bounds__(256, 3)
edge_kernel(const float* __restrict__ efeats,
            const int* __restrict__ u,
            const float* __restrict__ We,
            float* __restrict__ edge_out) {
    __nv_bfloat16* bs = (__nv_bfloat16*)smem_raw;
    __nv_bfloat16* A_hi = bs + SM_AHI;
    __nv_bfloat16* A_lo = bs + SM_ALO;
    __nv_bfloat16* B_hi = bs + SM_BHI;
    __nv_bfloat16* B_lo = bs + SM_BLO;
    int* u_s = (int*)(bs + SM_U_OFF);

    int t = threadIdx.x;
    int eb = blockIdx.x * 128;

    if (t < 128) u_s[t] = u[eb + t];

    {
        int row = t >> 1, half = t & 1;
        const float4* src = (const float4*)efeats + (size_t)(eb + row) * 16 + half * 8;
        // batch all 8 streaming loads (MLP 8), then convert+store
        float4 f[8];
#pragma unroll
        for (int i = 0; i < 8; i++) f[i] = ldg_cs4(src + i);
        unsigned* dh = (unsigned*)&A_hi[row * EPA + half * 32];
        unsigned* dl = (unsigned*)&A_lo[row * EPA + half * 32];
#pragma unroll
        for (int i = 0; i < 8; i++) {
            dh[i * 2 + 0] = pack_hi(f[i].x, f[i].y);
            dh[i * 2 + 1] = pack_hi(f[i].z, f[i].w);
            dl[i * 2 + 0] = pack_lo(f[i].x, f[i].y);
            dl[i * 2 + 1] = pack_lo(f[i].z, f[i].w);
        }
    }
    {
        int o = t >> 2, q = t & 3;
        const float4* src = (const float4*)We + o * 32 + 16 + q * 4;
        unsigned* dh = (unsigned*)&B_hi[o * EPA + q * 16];
        unsigned* dl = (unsigned*)&B_lo[o * EPA + q * 16];
#pragma unroll
        for (int i = 0; i < 4; i++) {
            float4 f = src[i];
            dh[i * 2 + 0] = pack_hi(f.x, f.y);
            dh[i * 2 + 1] = pack_hi(f.z, f.w);
            dl[i * 2 + 0] = pack_lo(f.x, f.y);
            dl[i * 2 + 1] = pack_lo(f.z, f.w);
        }
    }
    __syncthreads();

    int wid = t >> 5, lane = t & 31;
    int wm = wid & 3, wn = wid >> 2;
    int g = lane >> 2, tg = lane & 3;

    int a_row_off = lane & 15;
    int a_col_off = (lane >> 4) << 3;
    uint32_t ahi_base = smem_u32e(&A_hi[(wm * 32 + a_row_off) * EPA + a_col_off]);
    uint32_t alo_base = smem_u32e(&A_lo[(wm * 32 + a_row_off) * EPA + a_col_off]);
    int b_lane = lane & 15;
    int b_row_off = (b_lane < 8) ? b_lane : (b_lane - 8);
    int b_col_off = (b_lane < 8) ? 0 : 8;
    uint32_t bhi_base = smem_u32e(&B_hi[(wn * 32 + b_row_off) * EPA + b_col_off]);
    uint32_t blo_base = smem_u32e(&B_lo[(wn * 32 + b_row_off) * EPA + b_col_off]);

    float c[2][4][4] = {};

#pragma unroll
    for (int ks = 0; ks < 4; ks++) {
        uint32_t kb = ks * 32;
        unsigned ah[2][4], al[2][4];
        ldsm_x4(ah[0], ahi_base + kb);
        ldsm_x4(ah[1], ahi_base + kb + 16 * EPA * 2);
        ldsm_x4(al[0], alo_base + kb);
        ldsm_x4(al[1], alo_base + kb + 16 * EPA * 2);
        unsigned bh[4][2], bl[4][2];
#pragma unroll
        for (int nt = 0; nt < 4; nt++) {
            ldsm_x2(bh[nt], bhi_base + kb + nt * 8 * EPA * 2);
            ldsm_x2(bl[nt], blo_base + kb + nt * 8 * EPA * 2);
        }
#pragma unroll
        for (int mt = 0; mt < 2; mt++)
#pragma unroll
            for (int nt = 0; nt < 4; nt++) {
                mma_bf16(c[mt][nt], ah[mt], bh[nt]);
                mma_bf16(c[mt][nt], ah[mt], bl[nt]);
                mma_bf16(c[mt][nt], al[mt], bh[nt]);
            }
    }

    // Epilogue: batch ALL gathers first (MLP 16), then add + store
    float2 gv[2][4][2];
#pragma unroll
    for (int mt = 0; mt < 2; mt++) {
        int r0 = wm * 32 + mt * 16 + g;
        int u0 = u_s[r0], u1 = u_s[r0 + 8];
#pragma unroll
        for (int nt = 0; nt < 4; nt++) {
            int col = wn * 32 + nt * 8 + 2 * tg;
            gv[mt][nt][0] = *(const float2*)&g_hweb[(size_t)u0 * 64 + col];
            gv[mt][nt][1] = *(const float2*)&g_hweb[(size_t)u1 * 64 + col];
        }
    }
#pragma unroll
    for (int mt = 0; mt < 2; mt++) {
        int r0 = wm * 32 + mt * 16 + g;
        size_t e0 = (size_t)(eb + r0), e1 = (size_t)(eb + r0 + 8);
#pragma unroll
        for (int nt = 0; nt < 4; nt++) {
            int col = wn * 32 + nt * 8 + 2 * tg;
            stg_cs2(&edge_out[e0 * 64 + col],
                    c[mt][nt][0] + gv[mt][nt][0].x, c[mt][nt][1] + gv[mt][nt][0].y);
            stg_cs2(&edge_out[e1 * 64 + col],
                    c[mt][nt][2] + gv[mt][nt][1].x, c[mt][nt][3] + gv[mt][nt][1].y);
        }
    }
}

// ---------------------------------------------------------------------------
extern "C" void kernel_launch(void* const* d_in, const int* in_sizes, int n_in,
                              void* d_out, int out_size) {
    // inputs: [0]=nfeats (unused), [1]=efeats, [2]=u, [3]=v, [4]=Wn, [5]=bn, [6]=We, [7]=be
    const float* efeats = (const float*)d_in[1];
    const int*   u      = (const int*)d_in[2];
    const int*   v      = (const int*)d_in[3];
    const float* Wn     = (const float*)d_in[4];
    const float* bn     = (const float*)d_in[5];
    const float* We     = (const float*)d_in[6];
    const float* be     = (const float*)d_in[7];

    float* out      = (float*)d_out;
    float* h_out    = out;                               // [N,64]
    float* edge_out = out + (size_t)N_NODES * 64;        // [E,64]

    void* accp = nullptr; cudaGetSymbolAddress(&accp, g_acc);
    void* degp = nullptr; cudaGetSymbolAddress(&degp, g_deg);
    cudaMemsetAsync(accp, 0, sizeof(float) * 2 * N_NODES * D, 0);
    cudaMemsetAsync(degp, 0, sizeof(float) * 2 * N_NODES, 0);

    scatter_kernel<<<(E_EDGES * 16) / 256, 256>>>((const float4*)efeats, u, v);

    cudaFuncSetAttribute(node_kernel, cudaFuncAttributeMaxDynamicSharedMemorySize, N_SMEM_BYTES);
    node_kernel<<<(N_NODES + 127) / 128, 256, N_SMEM_BYTES>>>(Wn, bn, We, be, h_out);

    cudaFuncSetAttribute(edge_kernel, cudaFuncAttributeMaxDynamicSharedMemorySize, SM_EDGE_BYTES);
    edge_kernel<<<E_EDGES / 128, 256, SM_EDGE_BYTES>>>(efeats, u, We, edge_out);
}

// round 13
// speedup vs baseline: 1.5608x; 1.0411x over previous
#include <cuda_runtime.h>
#include <cuda_bf16.h>
#include <cstdint>

#define N_NODES 100000
#define E_EDGES 1600000
#define D 64
#define EPA 72       // bf16 row pitch for K=64 tiles (144 B)
#define EPN 136      // bf16 row pitch for K=128 tiles (272 B)
#define NTILES (E_EDGES / 128)   // 12500
#define EGRID 296                // persistent edge CTAs (2 per SM)

// Scratch (device globals — no dynamic allocation allowed)
__device__ float g_acc[2 * N_NODES * D];   // [v-sums | u-sums]
__device__ float g_deg[2 * N_NODES];       // [deg_v | deg_u]
__device__ float g_hweb[N_NODES * D];      // h @ We_h^T + be

extern __shared__ char smem_raw[];

// ---------------------------------------------------------------------------
// shared helpers
// ---------------------------------------------------------------------------
__device__ __forceinline__ void mma_bf16(float c[4], const unsigned a[4], const unsigned b[2]) {
    asm volatile(
        "mma.sync.aligned.m16n8k16.row.col.f32.bf16.bf16.f32 "
        "{%0,%1,%2,%3}, {%4,%5,%6,%7}, {%8,%9}, {%0,%1,%2,%3};"
        : "+f"(c[0]), "+f"(c[1]), "+f"(c[2]), "+f"(c[3])
        : "r"(a[0]), "r"(a[1]), "r"(a[2]), "r"(a[3]), "r"(b[0]), "r"(b[1]));
}
__device__ __forceinline__ void ldsm_x4(unsigned r[4], uint32_t addr) {
    asm volatile("ldmatrix.sync.aligned.m8n8.x4.shared.b16 {%0,%1,%2,%3}, [%4];"
                 : "=r"(r[0]), "=r"(r[1]), "=r"(r[2]), "=r"(r[3]) : "r"(addr));
}
__device__ __forceinline__ void ldsm_x2(unsigned r[2], uint32_t addr) {
    asm volatile("ldmatrix.sync.aligned.m8n8.x2.shared.b16 {%0,%1}, [%2];"
                 : "=r"(r[0]), "=r"(r[1]) : "r"(addr));
}
__device__ __forceinline__ unsigned pack_hi(float x, float y) {
    __nv_bfloat162 h(__float2bfloat16_rn(x), __float2bfloat16_rn(y));
    return *(unsigned*)&h;
}
__device__ __forceinline__ unsigned pack_lo(float x, float y) {
    __nv_bfloat16 hx = __float2bfloat16_rn(x), hy = __float2bfloat16_rn(y);
    __nv_bfloat162 l(__float2bfloat16_rn(x - __bfloat162float(hx)),
                     __float2bfloat16_rn(y - __bfloat162float(hy)));
    return *(unsigned*)&l;
}
static __device__ __forceinline__ uint32_t smem_u32e(const void* p) {
    uint32_t a;
    asm("{ .reg .u64 t; cvta.to.shared.u64 t, %1; cvt.u32.u64 %0, t; }" : "=r"(a) : "l"(p));
    return a;
}
__device__ __forceinline__ float4 ldg_cs4(const float4* p) { return __ldcs(p); }
__device__ __forceinline__ void stg_cs2(float* p, float x, float y) {
    __stcs((float2*)p, make_float2(x, y));
}

// ---------------------------------------------------------------------------
// Stage 1: scatter-add efeats into per-node sums (both directions) + degrees
// (L2-atomic-bound at its floor)
// ---------------------------------------------------------------------------
__device__ __forceinline__ void red_add_v4(float* p, float4 f) {
    asm volatile("red.global.add.v4.f32 [%0], {%1,%2,%3,%4};"
                 :: "l"(p), "f"(f.x), "f"(f.y), "f"(f.z), "f"(f.w) : "memory");
}

__global__ void scatter_kernel(const float4* __restrict__ ef4,
                               const int* __restrict__ u,
                               const int* __restrict__ v) {
    int idx = blockIdx.x * blockDim.x + threadIdx.x;  // exactly E*16
    int e = idx >> 4;
    int c = idx & 15;
    float4 f = ldg_cs4(ef4 + idx);
    int vv = v[e];
    int uu = u[e];
    red_add_v4(&g_acc[(vv << 6) + (c << 2)], f);
    red_add_v4(&g_acc[(N_NODES << 6) + (uu << 6) + (c << 2)], f);
    if (c == 0) {
        atomicAdd(&g_deg[vv], 1.0f);
        atomicAdd(&g_deg[N_NODES + uu], 1.0f);
    }
}

// ---------------------------------------------------------------------------
// Stage 2 (mma): per-node — means, h = relu(cat @ Wn^T + bn), hweb = h@We_h^T+be
// ---------------------------------------------------------------------------
#define N_A1HI 0
#define N_A1LO (128 * EPN)
#define N_B1HI (2 * 128 * EPN)
#define N_B1LO (2 * 128 * EPN + 64 * EPN)
#define N_ELEMS (2 * 128 * EPN + 2 * 64 * EPN)
#define N_SMEM_BYTES (N_ELEMS * 2)          // 104448
#define N_A2HI 0
#define N_A2LO (128 * EPA)
#define N_B2HI (2 * 128 * EPA)
#define N_B2LO (2 * 128 * EPA + 64 * EPA)

__global__ void __launch_bounds__(256, 2)
node_kernel(const float* __restrict__ Wn,
            const float* __restrict__ bn,
            const float* __restrict__ We,
            const float* __restrict__ be,
            float* __restrict__ h_out) {
    __nv_bfloat16* bs = (__nv_bfloat16*)smem_raw;
    int t = threadIdx.x;
    int nb = blockIdx.x * 128;

    {
        int row = t >> 1, half = t & 1;
        int n = nb + row;
        bool ok = (n < N_NODES);
        float s = 0.f;
        const float4* src = (const float4*)g_acc;
        if (half == 0) { if (ok) s = 1.0f / fmaxf(g_deg[n], 1.0f); src += (size_t)n * 16; }
        else           { if (ok) s = 1.0f / fmaxf(g_deg[N_NODES + n], 1.0f); src += (size_t)(N_NODES + n) * 16; }
        unsigned* dh = (unsigned*)&bs[N_A1HI + row * EPN + half * 64];
        unsigned* dl = (unsigned*)&bs[N_A1LO + row * EPN + half * 64];
#pragma unroll
        for (int i = 0; i < 16; i++) {
            float4 f = ok ? src[i] : make_float4(0.f, 0.f, 0.f, 0.f);
            f.x *= s; f.y *= s; f.z *= s; f.w *= s;
            dh[i * 2 + 0] = pack_hi(f.x, f.y);
            dh[i * 2 + 1] = pack_hi(f.z, f.w);
            dl[i * 2 + 0] = pack_lo(f.x, f.y);
            dl[i * 2 + 1] = pack_lo(f.z, f.w);
        }
    }
    {
        int o = t >> 2, q = t & 3;
        const float4* src = (const float4*)Wn + o * 32 + q * 8;
        unsigned* dh = (unsigned*)&bs[N_B1HI + o * EPN + q * 32];
        unsigned* dl = (unsigned*)&bs[N_B1LO + o * EPN + q * 32];
#pragma unroll
        for (int i = 0; i < 8; i++) {
            float4 f = src[i];
            dh[i * 2 + 0] = pack_hi(f.x, f.y);
            dh[i * 2 + 1] = pack_hi(f.z, f.w);
            dl[i * 2 + 0] = pack_lo(f.x, f.y);
            dl[i * 2 + 1] = pack_lo(f.z, f.w);
        }
    }
    __syncthreads();

    int wid = t >> 5, lane = t & 31;
    int wm = wid & 3, wn = wid >> 2;
    int g = lane >> 2, tg = lane & 3;

    int a_row_off = lane & 15;
    int a_col_off = (lane >> 4) << 3;
    int b_lane = lane & 15;
    int b_row_off = (b_lane < 8) ? b_lane : (b_lane - 8);
    int b_col_off = (b_lane < 8) ? 0 : 8;

    float c[2][4][4] = {};
    {
        uint32_t ahi = smem_u32e(&bs[N_A1HI + (wm * 32 + a_row_off) * EPN + a_col_off]);
        uint32_t alo = smem_u32e(&bs[N_A1LO + (wm * 32 + a_row_off) * EPN + a_col_off]);
        uint32_t bhi = smem_u32e(&bs[N_B1HI + (wn * 32 + b_row_off) * EPN + b_col_off]);
        uint32_t blo = smem_u32e(&bs[N_B1LO + (wn * 32 + b_row_off) * EPN + b_col_off]);
#pragma unroll
        for (int ks = 0; ks < 8; ks++) {
            uint32_t kb = ks * 32;
            unsigned ah[2][4], al[2][4];
            ldsm_x4(ah[0], ahi + kb);
            ldsm_x4(ah[1], ahi + kb + 16 * EPN * 2);
            ldsm_x4(al[0], alo + kb);
            ldsm_x4(al[1], alo + kb + 16 * EPN * 2);
            unsigned bh[4][2], bl[4][2];
#pragma unroll
            for (int nt = 0; nt < 4; nt++) {
                ldsm_x2(bh[nt], bhi + kb + nt * 8 * EPN * 2);
                ldsm_x2(bl[nt], blo + kb + nt * 8 * EPN * 2);
            }
#pragma unroll
            for (int mt = 0; mt < 2; mt++)
#pragma unroll
                for (int nt = 0; nt < 4; nt++) {
                    mma_bf16(c[mt][nt], ah[mt], bh[nt]);
                    mma_bf16(c[mt][nt], ah[mt], bl[nt]);
                    mma_bf16(c[mt][nt], al[mt], bh[nt]);
                }
        }
    }
    __syncthreads();

    // epilogue1: relu(+bn), write h (streaming), store A2 split of h
#pragma unroll
    for (int mt = 0; mt < 2; mt++) {
        int r0 = wm * 32 + mt * 16 + g;
        int r1 = r0 + 8;
#pragma unroll
        for (int nt = 0; nt < 4; nt++) {
            int col = wn * 32 + nt * 8 + 2 * tg;
            float2 bnv = *(const float2*)&bn[col];
            float v00 = fmaxf(c[mt][nt][0] + bnv.x, 0.f);
            float v01 = fmaxf(c[mt][nt][1] + bnv.y, 0.f);
            float v10 = fmaxf(c[mt][nt][2] + bnv.x, 0.f);
            float v11 = fmaxf(c[mt][nt][3] + bnv.y, 0.f);
            *(unsigned*)&bs[N_A2HI + r0 * EPA + col] = pack_hi(v00, v01);
            *(unsigned*)&bs[N_A2LO + r0 * EPA + col] = pack_lo(v00, v01);
            *(unsigned*)&bs[N_A2HI + r1 * EPA + col] = pack_hi(v10, v11);
            *(unsigned*)&bs[N_A2LO + r1 * EPA + col] = pack_lo(v10, v11);
            if (nb + r0 < N_NODES)
                stg_cs2(&h_out[(size_t)(nb + r0) * 64 + col], v00, v01);
            if (nb + r1 < N_NODES)
                stg_cs2(&h_out[(size_t)(nb + r1) * 64 + col], v10, v11);
        }
    }
    {
        int o = t >> 2, q = t & 3;
        const float4* src = (const float4*)We + o * 32 + q * 4;
        unsigned* dh = (unsigned*)&bs[N_B2HI + o * EPA + q * 16];
        unsigned* dl = (unsigned*)&bs[N_B2LO + o * EPA + q * 16];
#pragma unroll
        for (int i = 0; i < 4; i++) {
            float4 f = src[i];
            dh[i * 2 + 0] = pack_hi(f.x, f.y);
            dh[i * 2 + 1] = pack_hi(f.z, f.w);
            dl[i * 2 + 0] = pack_lo(f.x, f.y);
            dl[i * 2 + 1] = pack_lo(f.z, f.w);
        }
    }
    __syncthreads();

    float c2[2][4][4] = {};
    {
        uint32_t ahi = smem_u32e(&bs[N_A2HI + (wm * 32 + a_row_off) * EPA + a_col_off]);
        uint32_t alo = smem_u32e(&bs[N_A2LO + (wm * 32 + a_row_off) * EPA + a_col_off]);
        uint32_t bhi = smem_u32e(&bs[N_B2HI + (wn * 32 + b_row_off) * EPA + b_col_off]);
        uint32_t blo = smem_u32e(&bs[N_B2LO + (wn * 32 + b_row_off) * EPA + b_col_off]);
#pragma unroll
        for (int ks = 0; ks < 4; ks++) {
            uint32_t kb = ks * 32;
            unsigned ah[2][4], al[2][4];
            ldsm_x4(ah[0], ahi + kb);
            ldsm_x4(ah[1], ahi + kb + 16 * EPA * 2);
            ldsm_x4(al[0], alo + kb);
            ldsm_x4(al[1], alo + kb + 16 * EPA * 2);
            unsigned bh[4][2], bl[4][2];
#pragma unroll
            for (int nt = 0; nt < 4; nt++) {
                ldsm_x2(bh[nt], bhi + kb + nt * 8 * EPA * 2);
                ldsm_x2(bl[nt], blo + kb + nt * 8 * EPA * 2);
            }
#pragma unroll
            for (int mt = 0; mt < 2; mt++)
#pragma unroll
                for (int nt = 0; nt < 4; nt++) {
                    mma_bf16(c2[mt][nt], ah[mt], bh[nt]);
                    mma_bf16(c2[mt][nt], ah[mt], bl[nt]);
                    mma_bf16(c2[mt][nt], al[mt], bh[nt]);
                }
        }
    }

#pragma unroll
    for (int mt = 0; mt < 2; mt++) {
        int r0 = wm * 32 + mt * 16 + g;
        int r1 = r0 + 8;
#pragma unroll
        for (int nt = 0; nt < 4; nt++) {
            int col = wn * 32 + nt * 8 + 2 * tg;
            float2 bev = *(const float2*)&be[col];
            if (nb + r0 < N_NODES)
                *(float2*)&g_hweb[(size_t)(nb + r0) * 64 + col] =
                    make_float2(c2[mt][nt][0] + bev.x, c2[mt][nt][1] + bev.y);
            if (nb + r1 < N_NODES)
                *(float2*)&g_hweb[(size_t)(nb + r1) * 64 + col] =
                    make_float2(c2[mt][nt][2] + bev.x, c2[mt][nt][3] + bev.y);
        }
    }
}

// ---------------------------------------------------------------------------
// Stage 3: edge = hweb[u[e]] + efeats[e] @ We_e^T   (bf16x3, persistent CTAs,
// software-pipelined: tile i+1 LDG prefetch overlaps tile i compute)
// ---------------------------------------------------------------------------
#define SM_AHI 0
#define SM_ALO (128 * EPA)
#define SM_BHI (2 * 128 * EPA)
#define SM_BLO (2 * 128 * EPA + 64 * EPA)
#define SM_U_OFF (2 * 128 * EPA + 2 * 64 * EPA)
#define SM_EDGE_BYTES (SM_U_OFF * 2 + 128 * 4)

__global__ void __launch_bounds__(256, 2)
edge_kernel(const float* __restrict__ efeats,
            const int* __restrict__ u,
            const float* __restrict__ We,
            float* __restrict__ edge_out) {
    __nv_bfloat16* bs = (__nv_bfloat16*)smem_raw;
    __nv_bfloat16* A_hi = bs + SM_AHI;
    __nv_bfloat16* A_lo = bs + SM_ALO;
    __nv_bfloat16* B_hi = bs + SM_BHI;
    __nv_bfloat16* B_lo = bs + SM_BLO;
    int* u_s = (int*)(bs + SM_U_OFF);

    int t = threadIdx.x;
    int row = t >> 1, half = t & 1;

    // ---- B fill ONCE per CTA: We_e = We[:, 64:128]
    {
        int o = t >> 2, q = t & 3;
        const float4* src = (const float4*)We + o * 32 + 16 + q * 4;
        unsigned* dh = (unsigned*)&B_hi[o * EPA + q * 16];
        unsigned* dl = (unsigned*)&B_lo[o * EPA + q * 16];
#pragma unroll
        for (int i = 0; i < 4; i++) {
            float4 f = src[i];
            dh[i * 2 + 0] = pack_hi(f.x, f.y);
            dh[i * 2 + 1] = pack_hi(f.z, f.w);
            dl[i * 2 + 0] = pack_lo(f.x, f.y);
            dl[i * 2 + 1] = pack_lo(f.z, f.w);
        }
    }

    int wid = t >> 5, lane = t & 31;
    int wm = wid & 3, wn = wid >> 2;
    int g = lane >> 2, tg = lane & 3;

    int a_row_off = lane & 15;
    int a_col_off = (lane >> 4) << 3;
    uint32_t ahi_base = smem_u32e(&A_hi[(wm * 32 + a_row_off) * EPA + a_col_off]);
    uint32_t alo_base = smem_u32e(&A_lo[(wm * 32 + a_row_off) * EPA + a_col_off]);
    int b_lane = lane & 15;
    int b_row_off = (b_lane < 8) ? b_lane : (b_lane - 8);
    int b_col_off = (b_lane < 8) ? 0 : 8;
    uint32_t bhi_base = smem_u32e(&B_hi[(wn * 32 + b_row_off) * EPA + b_col_off]);
    uint32_t blo_base = smem_u32e(&B_lo[(wn * 32 + b_row_off) * EPA + b_col_off]);

    // ---- prefetch first tile into registers
    int tile = blockIdx.x;
    float4 pf[8];
    int pu = 0;
    {
        const float4* src = (const float4*)efeats + ((size_t)tile * 128 + row) * 16 + half * 8;
#pragma unroll
        for (int i = 0; i < 8; i++) pf[i] = ldg_cs4(src + i);
        if (t < 128) pu = u[tile * 128 + t];
    }

    while (tile < NTILES) {
        __syncthreads();   // prev mainloop done reading A; B fill visible (iter 0)

        // ---- convert prefetched regs -> A smem; publish u
        {
            unsigned* dh = (unsigned*)&A_hi[row * EPA + half * 32];
            unsigned* dl = (unsigned*)&A_lo[row * EPA + half * 32];
#pragma unroll
            for (int i = 0; i < 8; i++) {
                dh[i * 2 + 0] = pack_hi(pf[i].x, pf[i].y);
                dh[i * 2 + 1] = pack_hi(pf[i].z, pf[i].w);
                dl[i * 2 + 0] = pack_lo(pf[i].x, pf[i].y);
                dl[i * 2 + 1] = pack_lo(pf[i].z, pf[i].w);
            }
            if (t < 128) u_s[t] = pu;
        }
        __syncthreads();   // A tile + u_s ready

        size_t eb = (size_t)tile * 128;
        int ntile = tile + EGRID;

        // ---- prefetch next tile (LDG latency hides under mainloop+epilogue)
        if (ntile < NTILES) {
            const float4* src = (const float4*)efeats + ((size_t)ntile * 128 + row) * 16 + half * 8;
#pragma unroll
            for (int i = 0; i < 8; i++) pf[i] = ldg_cs4(src + i);
            if (t < 128) pu = u[ntile * 128 + t];
        }

        // ---- mainloop
        float c[2][4][4] = {};
#pragma unroll
        for (int ks = 0; ks < 4; ks++) {
            uint32_t kb = ks * 32;
            unsigned ah[2][4], al[2][4];
            ldsm_x4(ah[0], ahi_base + kb);
            ldsm_x4(ah[1], ahi_base + kb + 16 * EPA * 2);
            ldsm_x4(al[0], alo_base + kb);
            ldsm_x4(al[1], alo_base + kb + 16 * EPA * 2);
            unsigned bh[4][2], bl[4][2];
#pragma unroll
            for (int nt = 0; nt < 4; nt++) {
                ldsm_x2(bh[nt], bhi_base + kb + nt * 8 * EPA * 2);
                ldsm_x2(bl[nt], blo_base + kb + nt * 8 * EPA * 2);
            }
#pragma unroll
            for (int mt = 0; mt < 2; mt++)
#pragma unroll
                for (int nt = 0; nt < 4; nt++) {
                    mma_bf16(c[mt][nt], ah[mt], bh[nt]);
                    mma_bf16(c[mt][nt], ah[mt], bl[nt]);
                    mma_bf16(c[mt][nt], al[mt], bh[nt]);
                }
        }

        // ---- epilogue: batch gathers (MLP 16), then add + store
        float2 gv[2][4][2];
#pragma unroll
        for (int mt = 0; mt < 2; mt++) {
            int r0 = wm * 32 + mt * 16 + g;
            int u0 = u_s[r0], u1 = u_s[r0 + 8];
#pragma unroll
            for (int nt = 0; nt < 4; nt++) {
                int col = wn * 32 + nt * 8 + 2 * tg;
                gv[mt][nt][0] = *(const float2*)&g_hweb[(size_t)u0 * 64 + col];
                gv[mt][nt][1] = *(const float2*)&g_hweb[(size_t)u1 * 64 + col];
            }
        }
#pragma unroll
        for (int mt = 0; mt < 2; mt++) {
            int r0 = wm * 32 + mt * 16 + g;
            size_t e0 = eb + r0, e1 = eb + r0 + 8;
#pragma unroll
            for (int nt = 0; nt < 4; nt++) {
                int col = wn * 32 + nt * 8 + 2 * tg;
                stg_cs2(&edge_out[e0 * 64 + col],
                        c[mt][nt][0] + gv[mt][nt][0].x, c[mt][nt][1] + gv[mt][nt][0].y);
                stg_cs2(&edge_out[e1 * 64 + col],
                        c[mt][nt][2] + gv[mt][nt][1].x, c[mt][nt][3] + gv[mt][nt][1].y);
            }
        }

        tile = ntile;
    }
}

// ---------------------------------------------------------------------------
extern "C" void kernel_launch(void* const* d_in, const int* in_sizes, int n_in,
                              void* d_out, int out_size) {
    // inputs: [0]=nfeats (unused), [1]=efeats, [2]=u, [3]=v, [4]=Wn, [5]=bn, [6]=We, [7]=be
    const float* efeats = (const float*)d_in[1];
    const int*   u      = (const int*)d_in[2];
    const int*   v      = (const int*)d_in[3];
    const float* Wn     = (const float*)d_in[4];
    const float* bn     = (const float*)d_in[5];
    const float* We     = (const float*)d_in[6];
    const float* be     = (const float*)d_in[7];

    float* out      = (float*)d_out;
    float* h_out    = out;                               // [N,64]
    float* edge_out = out + (size_t)N_NODES * 64;        // [E,64]

    void* accp = nullptr; cudaGetSymbolAddress(&accp, g_acc);
    void* degp = nullptr; cudaGetSymbolAddress(&degp, g_deg);
    cudaMemsetAsync(accp, 0, sizeof(float) * 2 * N_NODES * D, 0);
    cudaMemsetAsync(degp, 0, sizeof(float) * 2 * N_NODES, 0);

    scatter_kernel<<<(E_EDGES * 16) / 256, 256>>>((const float4*)efeats, u, v);

    cudaFuncSetAttribute(node_kernel, cudaFuncAttributeMaxDynamicSharedMemorySize, N_SMEM_BYTES);
    node_kernel<<<(N_NODES + 127) / 128, 256, N_SMEM_BYTES>>>(Wn, bn, We, be, h_out);

    cudaFuncSetAttribute(edge_kernel, cudaFuncAttributeMaxDynamicSharedMemorySize, SM_EDGE_BYTES);
    edge_kernel<<<EGRID, 256, SM_EDGE_BYTES>>>(efeats, u, We, edge_out);
}